// round 11
// baseline (speedup 1.0000x reference)
#include <cuda_runtime.h>
#include <cuda_fp16.h>
#include <cstdint>

// Problem constants (fixed by setup_inputs)
#define BB 2
#define GG 16
#define N1 4096
#define S1 1024
#define NTOT 65536   // GG*N1
#define STOT 16384   // GG*S1
#define D1 128
#define D2 256
#define C1 256
#define C2 256
#define INCH 384
#define BN_CNT 8192  // BB*N1 samples per (segment, channel)
#define NSLOT 128    // BN partial slots per (segment, channel)

// -------- device scratch (no allocations allowed) --------
__device__ float  g_Y2t[BB * GG][S1][C1];      // 33.5 MB
__device__ int    g_idx[BB * GG][N1][3];
__device__ float  g_w[BB * GG][N1][3];
__device__ __half g_h1h[BB][C1][NTOT];         // 67 MB: layer-1 pre-act (fp16)
__device__ __half g_h2h[BB][C2][NTOT];         // 67 MB: layer-2 pre-act (fp16)
__device__ __half g_W1h[C1][INCH];             // fp16 weights (pre-converted)
__device__ __half g_W2h[C2][C1];
__device__ float  g_ps[2][GG][C1][NSLOT];      // BN partial sums
__device__ float  g_pq[2][GG][C1][NSLOT];      // BN partial sum-of-squares
__device__ float  g_scale1[GG][C1];
__device__ float  g_shift1[GG][C1];
__device__ float  g_scale2[GG][C2];
__device__ float  g_shift2[GG][C2];

// -------- fp16 helpers --------
__device__ __forceinline__ uint32_t f2h2(float lo, float hi) {
    uint32_t d;
    asm("cvt.rn.f16x2.f32 %0, %1, %2;" : "=r"(d) : "f"(hi), "f"(lo));
    return d;
}

__device__ __forceinline__ void hmma4(float c[4], const uint32_t a[4],
                                      uint32_t b0, uint32_t b1) {
    asm volatile(
        "mma.sync.aligned.m16n8k16.row.col.f32.f16.f16.f32 "
        "{%0,%1,%2,%3},{%4,%5,%6,%7},{%8,%9},{%0,%1,%2,%3};"
        : "+f"(c[0]), "+f"(c[1]), "+f"(c[2]), "+f"(c[3])
        : "r"(a[0]), "r"(a[1]), "r"(a[2]), "r"(a[3]), "r"(b0), "r"(b1));
}

// A-fragment via ldmatrix.x4.trans from As[k][m] (half, pitch 136);
// B fragments come from registers (loaded straight from global weights).
__device__ __forceinline__ void compute_stage(
    const __half (*As)[136], const uint32_t bf[4][2],
    float acc[4][4][4], int wm, int lane)
{
    const int q  = lane >> 3, r = lane & 7;
    const int mq = (q & 1) * 8;
    const int kq = (q >> 1) * 8;
    uint32_t af[4][4];
    #pragma unroll
    for (int i = 0; i < 4; i++) {
        const int m = wm * 64 + i * 16;
        uint32_t sa = (uint32_t)__cvta_generic_to_shared(&As[kq + r][m + mq]);
        asm volatile(
            "ldmatrix.sync.aligned.m8n8.x4.trans.shared.b16 {%0,%1,%2,%3}, [%4];"
            : "=r"(af[i][0]), "=r"(af[i][1]), "=r"(af[i][2]), "=r"(af[i][3])
            : "r"(sa));
    }
    #pragma unroll
    for (int j = 0; j < 4; j++)
        #pragma unroll
        for (int i = 0; i < 4; i++)
            hmma4(acc[i][j], af[i], bf[j][0], bf[j][1]);
}

// Per-thread BN partial reduction, then one deterministic store per slot.
__device__ __forceinline__ void epilogue_stats(
    float ssum[4][2], float sq[4][2], int layer, int gg, int n0,
    int wn, int lane, int slot)
{
    #pragma unroll
    for (int off = 4; off <= 16; off <<= 1) {
        #pragma unroll
        for (int j = 0; j < 4; j++) {
            ssum[j][0] += __shfl_xor_sync(0xffffffffu, ssum[j][0], off);
            ssum[j][1] += __shfl_xor_sync(0xffffffffu, ssum[j][1], off);
            sq[j][0]   += __shfl_xor_sync(0xffffffffu, sq[j][0], off);
            sq[j][1]   += __shfl_xor_sync(0xffffffffu, sq[j][1], off);
        }
    }
    if (lane < 4) {
        #pragma unroll
        for (int j = 0; j < 4; j++) {
            const int c = n0 + wn * 32 + j * 8 + 2 * lane;
            g_ps[layer][gg][c][slot]     = ssum[j][0];
            g_pq[layer][gg][c][slot]     = sq[j][0];
            g_ps[layer][gg][c + 1][slot] = ssum[j][1];
            g_pq[layer][gg][c + 1][slot] = sq[j][1];
        }
    }
}

// ============================================================
// K0: pre-convert weights to fp16 (runs once per launch, ~3 us).
// ============================================================
__global__ __launch_bounds__(256) void prep_w(
    const float* __restrict__ W1, const float* __restrict__ W2)
{
    const int t = blockIdx.x * 256 + threadIdx.x;
    if (t < C1 * INCH) (&g_W1h[0][0])[t] = __float2half(W1[t]);
    const int u = t - C1 * INCH;
    if (u >= 0 && u < C2 * C1) (&g_W2h[0][0])[u] = __float2half(W2[u]);
}

// ============================================================
// K1: 3-NN + inverse-distance weights (fp32, unchanged).
// ============================================================
__global__ __launch_bounds__(256) void knn_kernel(
    const float* __restrict__ xyz1, const float* __restrict__ xyz2)
{
    __shared__ float sx[S1], sy[S1], sz[S1];
    const int bg = blockIdx.y;
    const int b = bg >> 4, g = bg & 15;
    const float* x2 = xyz2 + (size_t)b * 3 * STOT + g * S1;
    for (int s = threadIdx.x; s < S1; s += 256) {
        sx[s] = x2[s];
        sy[s] = x2[STOT + s];
        sz[s] = x2[2 * STOT + s];
    }
    __syncthreads();

    const int n = blockIdx.x * 256 + threadIdx.x;
    const float* x1 = xyz1 + (size_t)b * 3 * NTOT + g * N1 + n;
    const float qx = x1[0], qy = x1[NTOT], qz = x1[2 * NTOT];

    float d0 = 3.4e38f, d1 = 3.4e38f, d2 = 3.4e38f;
    int i0 = 0, i1 = 0, i2 = 0;
    #pragma unroll 4
    for (int s = 0; s < S1; s++) {
        const float dx = qx - sx[s];
        const float dy = qy - sy[s];
        const float dz = qz - sz[s];
        const float d = fmaf(dx, dx, fmaf(dy, dy, dz * dz));
        if (d < d2) {
            if (d < d1) {
                if (d < d0) { d2 = d1; i2 = i1; d1 = d0; i1 = i0; d0 = d; i0 = s; }
                else        { d2 = d1; i2 = i1; d1 = d;  i1 = s; }
            } else          { d2 = d;  i2 = s; }
        }
    }
    float w0 = 1.0f / (d0 + 1e-8f);
    float w1 = 1.0f / (d1 + 1e-8f);
    float w2 = 1.0f / (d2 + 1e-8f);
    const float inv = 1.0f / (w0 + w1 + w2);
    g_idx[bg][n][0] = i0; g_idx[bg][n][1] = i1; g_idx[bg][n][2] = i2;
    g_w[bg][n][0] = w0 * inv; g_w[bg][n][1] = w1 * inv; g_w[bg][n][2] = w2 * inv;
}

// A staging (fp32 -> fp16): 256 threads move 16k x 128m per stage.
#define STAGE_STORE_A(Asb, PA)                                          \
    {                                                                   \
        _Pragma("unroll")                                               \
        for (int v = 0; v < 2; v++) {                                   \
            const int ka = (tid >> 5) + v * 8, ma = (tid & 31) * 4;     \
            uint2 h;                                                    \
            h.x = f2h2(PA[v].x, PA[v].y);                               \
            h.y = f2h2(PA[v].z, PA[v].w);                               \
            *(uint2*)&Asb[ka][ma] = h;                                  \
        }                                                               \
    }

// B fragment load from global fp16 weights for one stage (4 j x 2 regs).
#define LOAD_BF(dst, bbase, pitch, kofs)                                \
    {                                                                   \
        _Pragma("unroll")                                               \
        for (int j = 0; j < 4; j++) {                                   \
            const __half* p = (bbase) + (size_t)j * 8 * (pitch) + (kofs); \
            dst[j][0] = *(const uint32_t*)p;                            \
            dst[j][1] = *(const uint32_t*)(p + 8);                      \
        }                                                               \
    }

#define SNAP_BF(dst, src)                                               \
    {                                                                   \
        _Pragma("unroll")                                               \
        for (int j = 0; j < 4; j++) { dst[j][0] = src[j][0]; dst[j][1] = src[j][1]; } \
    }

// ============================================================
// K2: Y2t = (W1b @ p2)^T  (fp16 MMA, K=256). grid = (8, 2, 32)
// ============================================================
__global__ __launch_bounds__(256, 2) void y2t_mma(
    const float* __restrict__ p2)
{
    __shared__ __half As[2][16][136];
    const int m0 = blockIdx.x * 128, n0 = blockIdx.y * 128;
    const int bg = blockIdx.z, b = bg >> 4, gg = bg & 15;
    const int tid = threadIdx.x, lane = tid & 31, wid = tid >> 5;
    const int wm = wid & 1, wn = wid >> 1, g = lane >> 2, tg = lane & 3;

    const float*  Ab = p2 + (size_t)b * D2 * STOT + gg * S1 + m0;
    const __half* Bbase = &g_W1h[n0 + wn * 32 + g][128 + 2 * tg];

    float acc[4][4][4] = {};
    float4 pa[2][2];
    uint32_t bf[4][2];
    #pragma unroll
    for (int s = 0; s < 2; s++)
        #pragma unroll
        for (int v = 0; v < 2; v++)
            pa[s][v] = *(const float4*)(Ab + (size_t)(16 * s + (tid >> 5) + v * 8) * STOT + (tid & 31) * 4);
    LOAD_BF(bf, Bbase, INCH, 0);

    #pragma unroll 2
    for (int s = 0; s < 16; s++) {
        const int set = s & 1;
        STAGE_STORE_A(As[set], pa[set]);
        __syncthreads();
        uint32_t bcur[4][2];
        SNAP_BF(bcur, bf);
        if (s + 1 < 16) LOAD_BF(bf, Bbase, INCH, 16 * (s + 1));
        if (s + 2 < 16) {
            const int kt = 16 * (s + 2);
            #pragma unroll
            for (int v = 0; v < 2; v++)
                pa[set][v] = *(const float4*)(Ab + (size_t)(kt + (tid >> 5) + v * 8) * STOT + (tid & 31) * 4);
        }
        compute_stage(As[set], bcur, acc, wm, lane);
    }
    #pragma unroll
    for (int i = 0; i < 4; i++) {
        const int s = m0 + wm * 64 + i * 16 + g;
        #pragma unroll
        for (int j = 0; j < 4; j++) {
            const int o = n0 + wn * 32 + j * 8 + 2 * tg;
            *(float2*)&g_Y2t[bg][s][o]     = make_float2(acc[i][j][0], acc[i][j][1]);
            *(float2*)&g_Y2t[bg][s + 8][o] = make_float2(acc[i][j][2], acc[i][j][3]);
        }
    }
}

// ============================================================
// K3: h1_pre = W1a @ p1 + interp(Y2t) + b1 -> fp16 store + BN1 partials.
// (fp16 MMA, K=128). grid = (32, 2, 32)
// ============================================================
__global__ __launch_bounds__(256, 2) void h1_mma(
    const float* __restrict__ p1, const float* __restrict__ b1)
{
    __shared__ __half As[2][16][136];
    const int m0 = blockIdx.x * 128, n0 = blockIdx.y * 128;
    const int bg = blockIdx.z, b = bg >> 4, gg = bg & 15;
    const int tid = threadIdx.x, lane = tid & 31, wid = tid >> 5;
    const int wm = wid & 1, wn = wid >> 1, g = lane >> 2, tg = lane & 3;

    const float*  Ab = p1 + (size_t)b * D1 * NTOT + gg * N1 + m0;
    const __half* Bbase = &g_W1h[n0 + wn * 32 + g][2 * tg];

    float acc[4][4][4] = {};
    float4 pa[2][2];
    uint32_t bf[4][2];
    #pragma unroll
    for (int s = 0; s < 2; s++)
        #pragma unroll
        for (int v = 0; v < 2; v++)
            pa[s][v] = *(const float4*)(Ab + (size_t)(16 * s + (tid >> 5) + v * 8) * NTOT + (tid & 31) * 4);
    LOAD_BF(bf, Bbase, INCH, 0);

    #pragma unroll 2
    for (int s = 0; s < 8; s++) {
        const int set = s & 1;
        STAGE_STORE_A(As[set], pa[set]);
        __syncthreads();
        uint32_t bcur[4][2];
        SNAP_BF(bcur, bf);
        if (s + 1 < 8) LOAD_BF(bf, Bbase, INCH, 16 * (s + 1));
        if (s + 2 < 8) {
            const int kt = 16 * (s + 2);
            #pragma unroll
            for (int v = 0; v < 2; v++)
                pa[set][v] = *(const float4*)(Ab + (size_t)(kt + (tid >> 5) + v * 8) * NTOT + (tid & 31) * 4);
        }
        compute_stage(As[set], bcur, acc, wm, lane);
    }

    // fp32 epilogue: interp(Y2t) + bias; fp16 store; BN1 partial stats.
    float ssum[4][2] = {}, sq[4][2] = {};
    #pragma unroll
    for (int i = 0; i < 4; i++) {
        const int rA = m0 + wm * 64 + i * 16 + g;
        const int rB = rA + 8;
        int   iA[3], iB[3];
        float wA[3], wB[3];
        #pragma unroll
        for (int k = 0; k < 3; k++) {
            iA[k] = g_idx[bg][rA][k]; wA[k] = g_w[bg][rA][k];
            iB[k] = g_idx[bg][rB][k]; wB[k] = g_w[bg][rB][k];
        }
        #pragma unroll
        for (int j = 0; j < 4; j++) {
            const int o = n0 + wn * 32 + j * 8 + 2 * tg;
            float c0 = acc[i][j][0], c1 = acc[i][j][1];
            float c2 = acc[i][j][2], c3 = acc[i][j][3];
            #pragma unroll
            for (int k = 0; k < 3; k++) {
                const float2 yA = *(const float2*)&g_Y2t[bg][iA[k]][o];
                c0 = fmaf(wA[k], yA.x, c0); c1 = fmaf(wA[k], yA.y, c1);
                const float2 yB = *(const float2*)&g_Y2t[bg][iB[k]][o];
                c2 = fmaf(wB[k], yB.x, c2); c3 = fmaf(wB[k], yB.y, c3);
            }
            const float2 bo = *(const float2*)(b1 + o);
            c0 += bo.x; c1 += bo.y; c2 += bo.x; c3 += bo.y;
            g_h1h[b][o][gg * N1 + rA]     = __float2half(c0);
            g_h1h[b][o + 1][gg * N1 + rA] = __float2half(c1);
            g_h1h[b][o][gg * N1 + rB]     = __float2half(c2);
            g_h1h[b][o + 1][gg * N1 + rB] = __float2half(c3);
            ssum[j][0] += c0 + c2; sq[j][0] += c0 * c0 + c2 * c2;
            ssum[j][1] += c1 + c3; sq[j][1] += c1 * c1 + c3 * c3;
        }
    }
    epilogue_stats(ssum, sq, 0, gg, n0, wn, lane, b * 64 + blockIdx.x * 2 + wm);
}

// ============================================================
// K4/K6: finish BN stats (deterministic tree over NSLOT partials).
// ============================================================
__global__ __launch_bounds__(NSLOT) void bnfinish_kernel(
    const float* __restrict__ gamma, const float* __restrict__ beta, int layer)
{
    const int c = blockIdx.x, gg = blockIdx.y, tid = threadIdx.x;
    __shared__ float rs[NSLOT], rq[NSLOT];
    rs[tid] = g_ps[layer][gg][c][tid];
    rq[tid] = g_pq[layer][gg][c][tid];
    __syncthreads();
    for (int off = NSLOT / 2; off; off >>= 1) {
        if (tid < off) { rs[tid] += rs[tid + off]; rq[tid] += rq[tid + off]; }
        __syncthreads();
    }
    if (tid == 0) {
        const float inv = 1.0f / (float)BN_CNT;
        const float mean = rs[0] * inv;
        const float var = rq[0] * inv - mean * mean;
        const float sc = gamma[c] * rsqrtf(var + 1e-5f);
        const float sh = beta[c] - mean * sc;
        if (layer == 0) { g_scale1[gg][c] = sc; g_shift1[gg][c] = sh; }
        else            { g_scale2[gg][c] = sc; g_shift2[gg][c] = sh; }
    }
}

// ============================================================
// K5: h2_pre = W2 @ relu(bn1(h1)) + b2 -> fp16 store + BN2 partials.
// A fp16 with BN1+ReLU in half2; B fragments from global fp16 W2.
// grid = (32, 2, 32)
// ============================================================
__global__ __launch_bounds__(256, 2) void gemm2_mma(
    const float* __restrict__ b2)
{
    __shared__ __half As[2][16][136];
    const int m0 = blockIdx.x * 128, n0 = blockIdx.y * 128;
    const int bg = blockIdx.z, b = bg >> 4, gg = bg & 15;
    const int tid = threadIdx.x, lane = tid & 31, wid = tid >> 5;
    const int wm = wid & 1, wn = wid >> 1, g = lane >> 2, tg = lane & 3;

    const __half*  Abh = &g_h1h[b][0][gg * N1 + m0];
    const __half*  Bbase = &g_W2h[n0 + wn * 32 + g][2 * tg];

    float acc[4][4][4] = {};
    const int ka = tid >> 4, ma = (tid & 15) * 8;
    uint4 pha[2];
    __half2 psc[2], psh[2];
    uint32_t bf[4][2];
    #pragma unroll
    for (int s = 0; s < 2; s++) {
        const int c = 16 * s + ka;
        pha[s] = *(const uint4*)(Abh + (size_t)c * NTOT + ma);
        psc[s] = __float2half2_rn(g_scale1[gg][c]);
        psh[s] = __float2half2_rn(g_shift1[gg][c]);
    }
    LOAD_BF(bf, Bbase, C1, 0);

    const __half2 hz = __float2half2_rn(0.f);
    #pragma unroll 2
    for (int s = 0; s < 16; s++) {
        const int set = s & 1;
        // A: BN1 + ReLU in half2, store to smem
        {
            const __half2* hp = (const __half2*)&pha[set];
            uint4 st;
            __half2* sp = (__half2*)&st;
            #pragma unroll
            for (int u = 0; u < 4; u++)
                sp[u] = __hmax2(__hfma2(hp[u], psc[set], psh[set]), hz);
            *(uint4*)&As[set][ka][ma] = st;
        }
        __syncthreads();
        uint32_t bcur[4][2];
        SNAP_BF(bcur, bf);
        if (s + 1 < 16) LOAD_BF(bf, Bbase, C1, 16 * (s + 1));
        if (s + 2 < 16) {
            const int c = 16 * (s + 2) + ka;
            pha[set] = *(const uint4*)(Abh + (size_t)c * NTOT + ma);
            psc[set] = __float2half2_rn(g_scale1[gg][c]);
            psh[set] = __float2half2_rn(g_shift1[gg][c]);
        }
        compute_stage(As[set], bcur, acc, wm, lane);
    }

    // Epilogue: +bias, fp16 store to g_h2h, BN2 partial stats.
    float ssum[4][2] = {}, sq[4][2] = {};
    #pragma unroll
    for (int i = 0; i < 4; i++) {
        const int rA = m0 + wm * 64 + i * 16 + g;
        const int rB = rA + 8;
        #pragma unroll
        for (int j = 0; j < 4; j++) {
            const int o = n0 + wn * 32 + j * 8 + 2 * tg;
            const float2 bo = *(const float2*)(b2 + o);
            const float c0 = acc[i][j][0] + bo.x;
            const float c1 = acc[i][j][1] + bo.y;
            const float c2 = acc[i][j][2] + bo.x;
            const float c3 = acc[i][j][3] + bo.y;
            g_h2h[b][o][gg * N1 + rA]     = __float2half(c0);
            g_h2h[b][o + 1][gg * N1 + rA] = __float2half(c1);
            g_h2h[b][o][gg * N1 + rB]     = __float2half(c2);
            g_h2h[b][o + 1][gg * N1 + rB] = __float2half(c3);
            ssum[j][0] += c0 + c2; sq[j][0] += c0 * c0 + c2 * c2;
            ssum[j][1] += c1 + c3; sq[j][1] += c1 * c1 + c3 * c3;
        }
    }
    epilogue_stats(ssum, sq, 1, gg, n0, wn, lane, b * 64 + blockIdx.x * 2 + wm);
}

// ============================================================
// K7: BN2 + ReLU: fp16 g_h2h -> fp32 d_out.
// ============================================================
__global__ __launch_bounds__(256) void bnfinal_kernel(float* __restrict__ out)
{
    const size_t f4 = (size_t)blockIdx.x * 256 + threadIdx.x;
    const size_t f = f4 * 4;
    const int o = (int)((f >> 16) & 255);
    const int g = (int)((f >> 12) & 15);
    const float sc = g_scale2[g][o];
    const float sh = g_shift2[g][o];
    const uint2 hraw = ((const uint2*)&g_h2h[0][0][0])[f4];
    const float2 f0 = __half22float2(*(const __half2*)&hraw.x);
    const float2 f1 = __half22float2(*(const __half2*)&hraw.y);
    float4 v;
    v.x = fmaxf(fmaf(f0.x, sc, sh), 0.f);
    v.y = fmaxf(fmaf(f0.y, sc, sh), 0.f);
    v.z = fmaxf(fmaf(f1.x, sc, sh), 0.f);
    v.w = fmaxf(fmaf(f1.y, sc, sh), 0.f);
    ((float4*)out)[f4] = v;
}

// ============================================================
extern "C" void kernel_launch(void* const* d_in, const int* in_sizes, int n_in,
                              void* d_out, int out_size)
{
    (void)in_sizes; (void)n_in; (void)out_size;
    const float* xyz1    = (const float*)d_in[0];
    const float* points1 = (const float*)d_in[1];
    const float* xyz2    = (const float*)d_in[3];
    const float* points2 = (const float*)d_in[4];
    const float* W1      = (const float*)d_in[6];
    const float* b1      = (const float*)d_in[7];
    const float* gamma1  = (const float*)d_in[8];
    const float* beta1   = (const float*)d_in[9];
    const float* W2      = (const float*)d_in[10];
    const float* b2      = (const float*)d_in[11];
    const float* gamma2  = (const float*)d_in[12];
    const float* beta2   = (const float*)d_in[13];
    float* out = (float*)d_out;

    prep_w<<<(C1 * INCH + C2 * C1 + 255) / 256, 256>>>(W1, W2);
    knn_kernel<<<dim3(N1 / 256, BB * GG), 256>>>(xyz1, xyz2);
    y2t_mma<<<dim3(S1 / 128, C1 / 128, BB * GG), 256>>>(points2);
    h1_mma<<<dim3(N1 / 128, C1 / 128, BB * GG), 256>>>(points1, b1);
    bnfinish_kernel<<<dim3(C1, GG), NSLOT>>>(gamma1, beta1, 0);
    gemm2_mma<<<dim3(N1 / 128, C2 / 128, BB * GG), 256>>>(b2);
    bnfinish_kernel<<<dim3(C2, GG), NSLOT>>>(gamma2, beta2, 1);
    bnfinal_kernel<<<(BB * C2 * NTOT) / 4 / 256, 256>>>(out);
}

// round 13
// speedup vs baseline: 1.1517x; 1.1517x over previous
#include <cuda_runtime.h>
#include <cuda_fp16.h>
#include <cstdint>

// Problem constants (fixed by setup_inputs)
#define BB 2
#define GG 16
#define N1 4096
#define S1 1024
#define NTOT 65536   // GG*N1
#define STOT 16384   // GG*S1
#define D1 128
#define D2 256
#define C1 256
#define C2 256
#define INCH 384
#define BN_CNT 8192  // BB*N1 samples per (segment, channel)
#define NSLOT 128    // BN partial slots per (segment, channel)

// -------- device scratch (no allocations allowed) --------
__device__ __half2 g_Y2th[BB * GG][S1][C1 / 2]; // 16.7 MB: (W1b @ p2)^T, fp16
__device__ int    g_idx[BB * GG][N1][3];
__device__ float  g_w[BB * GG][N1][3];
__device__ __half g_h1h[BB][C1][NTOT];         // 67 MB: layer-1 pre-act (fp16)
__device__ __half g_h2h[BB][C2][NTOT];         // 67 MB: layer-2 pre-act (fp16)
__device__ __half g_W1h[C1][INCH];             // fp16 weights (pre-converted)
__device__ __half g_W2h[C2][C1];
__device__ float  g_ps[2][GG][C1][NSLOT];      // BN partial sums
__device__ float  g_pq[2][GG][C1][NSLOT];      // BN partial sum-of-squares
__device__ float  g_scale1[GG][C1];
__device__ float  g_shift1[GG][C1];
__device__ float  g_scale2[GG][C2];
__device__ float  g_shift2[GG][C2];

// -------- fp16 helpers --------
__device__ __forceinline__ uint32_t f2h2(float lo, float hi) {
    uint32_t d;
    asm("cvt.rn.f16x2.f32 %0, %1, %2;" : "=r"(d) : "f"(hi), "f"(lo));
    return d;
}

__device__ __forceinline__ void hmma4(float c[4], const uint32_t a[4],
                                      uint32_t b0, uint32_t b1) {
    asm volatile(
        "mma.sync.aligned.m16n8k16.row.col.f32.f16.f16.f32 "
        "{%0,%1,%2,%3},{%4,%5,%6,%7},{%8,%9},{%0,%1,%2,%3};"
        : "+f"(c[0]), "+f"(c[1]), "+f"(c[2]), "+f"(c[3])
        : "r"(a[0]), "r"(a[1]), "r"(a[2]), "r"(a[3]), "r"(b0), "r"(b1));
}

// A-fragment via ldmatrix.x4.trans from As[k][m] (half, pitch 136)
// B-fragment via LDS.32 from Bs[n][k] (half, pitch 24) — conflict-free.
__device__ __forceinline__ void compute_stage(
    const __half (*As)[136], const __half (*Bs)[24],
    float acc[4][4][4], int wm, int wn, int g, int tg, int lane)
{
    const int q  = lane >> 3, r = lane & 7;
    const int mq = (q & 1) * 8;
    const int kq = (q >> 1) * 8;
    uint32_t af[4][4];
    #pragma unroll
    for (int i = 0; i < 4; i++) {
        const int m = wm * 64 + i * 16;
        uint32_t sa = (uint32_t)__cvta_generic_to_shared(&As[kq + r][m + mq]);
        asm volatile(
            "ldmatrix.sync.aligned.m8n8.x4.trans.shared.b16 {%0,%1,%2,%3}, [%4];"
            : "=r"(af[i][0]), "=r"(af[i][1]), "=r"(af[i][2]), "=r"(af[i][3])
            : "r"(sa));
    }
    #pragma unroll
    for (int j = 0; j < 4; j++) {
        const int n = wn * 32 + j * 8 + g;
        const uint32_t b0 = *(const uint32_t*)&Bs[n][2 * tg];
        const uint32_t b1 = *(const uint32_t*)&Bs[n][2 * tg + 8];
        #pragma unroll
        for (int i = 0; i < 4; i++)
            hmma4(acc[i][j], af[i], b0, b1);
    }
}

// Per-thread BN partial reduction, then one deterministic store per slot.
__device__ __forceinline__ void epilogue_stats(
    float ssum[4][2], float sq[4][2], int layer, int gg, int n0,
    int wn, int lane, int slot)
{
    #pragma unroll
    for (int off = 4; off <= 16; off <<= 1) {
        #pragma unroll
        for (int j = 0; j < 4; j++) {
            ssum[j][0] += __shfl_xor_sync(0xffffffffu, ssum[j][0], off);
            ssum[j][1] += __shfl_xor_sync(0xffffffffu, ssum[j][1], off);
            sq[j][0]   += __shfl_xor_sync(0xffffffffu, sq[j][0], off);
            sq[j][1]   += __shfl_xor_sync(0xffffffffu, sq[j][1], off);
        }
    }
    if (lane < 4) {
        #pragma unroll
        for (int j = 0; j < 4; j++) {
            const int c = n0 + wn * 32 + j * 8 + 2 * lane;
            g_ps[layer][gg][c][slot]     = ssum[j][0];
            g_pq[layer][gg][c][slot]     = sq[j][0];
            g_ps[layer][gg][c + 1][slot] = ssum[j][1];
            g_pq[layer][gg][c + 1][slot] = sq[j][1];
        }
    }
}

// ============================================================
// K0: pre-convert weights to fp16 (runs once per launch, ~3 us).
// ============================================================
__global__ __launch_bounds__(256) void prep_w(
    const float* __restrict__ W1, const float* __restrict__ W2)
{
    const int t = blockIdx.x * 256 + threadIdx.x;
    if (t < C1 * INCH) (&g_W1h[0][0])[t] = __float2half(W1[t]);
    const int u = t - C1 * INCH;
    if (u >= 0 && u < C2 * C1) (&g_W2h[0][0])[u] = __float2half(W2[u]);
}

// ============================================================
// K1: 3-NN + inverse-distance weights (fp32, unchanged).
// ============================================================
__global__ __launch_bounds__(256) void knn_kernel(
    const float* __restrict__ xyz1, const float* __restrict__ xyz2)
{
    __shared__ float sx[S1], sy[S1], sz[S1];
    const int bg = blockIdx.y;
    const int b = bg >> 4, g = bg & 15;
    const float* x2 = xyz2 + (size_t)b * 3 * STOT + g * S1;
    for (int s = threadIdx.x; s < S1; s += 256) {
        sx[s] = x2[s];
        sy[s] = x2[STOT + s];
        sz[s] = x2[2 * STOT + s];
    }
    __syncthreads();

    const int n = blockIdx.x * 256 + threadIdx.x;
    const float* x1 = xyz1 + (size_t)b * 3 * NTOT + g * N1 + n;
    const float qx = x1[0], qy = x1[NTOT], qz = x1[2 * NTOT];

    float d0 = 3.4e38f, d1 = 3.4e38f, d2 = 3.4e38f;
    int i0 = 0, i1 = 0, i2 = 0;
    #pragma unroll 4
    for (int s = 0; s < S1; s++) {
        const float dx = qx - sx[s];
        const float dy = qy - sy[s];
        const float dz = qz - sz[s];
        const float d = fmaf(dx, dx, fmaf(dy, dy, dz * dz));
        if (d < d2) {
            if (d < d1) {
                if (d < d0) { d2 = d1; i2 = i1; d1 = d0; i1 = i0; d0 = d; i0 = s; }
                else        { d2 = d1; i2 = i1; d1 = d;  i1 = s; }
            } else          { d2 = d;  i2 = s; }
        }
    }
    float w0 = 1.0f / (d0 + 1e-8f);
    float w1 = 1.0f / (d1 + 1e-8f);
    float w2 = 1.0f / (d2 + 1e-8f);
    const float inv = 1.0f / (w0 + w1 + w2);
    g_idx[bg][n][0] = i0; g_idx[bg][n][1] = i1; g_idx[bg][n][2] = i2;
    g_w[bg][n][0] = w0 * inv; g_w[bg][n][1] = w1 * inv; g_w[bg][n][2] = w2 * inv;
}

// A staging (fp32 -> fp16): 256 threads move 16k x 128m per stage.
#define STAGE_STORE_A(Asb, PA)                                          \
    {                                                                   \
        _Pragma("unroll")                                               \
        for (int v = 0; v < 2; v++) {                                   \
            const int kaa = (tid >> 5) + v * 8, maa = (tid & 31) * 4;   \
            uint2 h;                                                    \
            h.x = f2h2(PA[v].x, PA[v].y);                               \
            h.y = f2h2(PA[v].z, PA[v].w);                               \
            *(uint2*)&Asb[kaa][maa] = h;                                \
        }                                                               \
    }

// ============================================================
// K2: Y2t = (W1b @ p2)^T  (fp16 MMA, K=256). grid = (8, 2, 32)
// B staged to smem from fp16 weights: 1 LDG.128 + 1 STS.128 / thread / stage.
// ============================================================
__global__ __launch_bounds__(256, 2) void y2t_mma(
    const float* __restrict__ p2)
{
    __shared__ __half As[2][16][136];
    __shared__ __half Bs[2][128][24];
    const int m0 = blockIdx.x * 128, n0 = blockIdx.y * 128;
    const int bg = blockIdx.z, b = bg >> 4, gg = bg & 15;
    const int tid = threadIdx.x, lane = tid & 31, wid = tid >> 5;
    const int wm = wid & 1, wn = wid >> 1, g = lane >> 2, tg = lane & 3;

    const float*  Ab = p2 + (size_t)b * D2 * STOT + gg * S1 + m0;
    const __half* Bg = &g_W1h[n0 + (tid >> 1)][128 + (tid & 1) * 8];
    const int nb = tid >> 1, kb = (tid & 1) * 8;

    float acc[4][4][4] = {};
    float4 pa[2][2];
    uint4  pbh[2];
    #pragma unroll
    for (int s = 0; s < 2; s++) {
        #pragma unroll
        for (int v = 0; v < 2; v++)
            pa[s][v] = *(const float4*)(Ab + (size_t)(16 * s + (tid >> 5) + v * 8) * STOT + (tid & 31) * 4);
        pbh[s] = *(const uint4*)(Bg + 16 * s);
    }
    #pragma unroll 2
    for (int s = 0; s < 16; s++) {
        const int set = s & 1;
        STAGE_STORE_A(As[set], pa[set]);
        *(uint4*)&Bs[set][nb][kb] = pbh[set];
        __syncthreads();
        if (s + 2 < 16) {
            const int kt = 16 * (s + 2);
            #pragma unroll
            for (int v = 0; v < 2; v++)
                pa[set][v] = *(const float4*)(Ab + (size_t)(kt + (tid >> 5) + v * 8) * STOT + (tid & 31) * 4);
            pbh[set] = *(const uint4*)(Bg + kt);
        }
        compute_stage(As[set], Bs[set], acc, wm, wn, g, tg, lane);
    }
    #pragma unroll
    for (int i = 0; i < 4; i++) {
        const int s = m0 + wm * 64 + i * 16 + g;
        #pragma unroll
        for (int j = 0; j < 4; j++) {
            const int oh = (n0 + wn * 32 + j * 8) / 2 + tg;
            g_Y2th[bg][s][oh]     = __floats2half2_rn(acc[i][j][0], acc[i][j][1]);
            g_Y2th[bg][s + 8][oh] = __floats2half2_rn(acc[i][j][2], acc[i][j][3]);
        }
    }
}

// ============================================================
// K3: h1_pre = W1a @ p1 + interp(Y2t) + b1 -> fp16 store + BN1 partials.
// (fp16 MMA, K=128). grid = (32, 2, 32)
// ============================================================
__global__ __launch_bounds__(256, 2) void h1_mma(
    const float* __restrict__ p1, const float* __restrict__ b1)
{
    __shared__ __half As[2][16][136];
    __shared__ __half Bs[2][128][24];
    const int m0 = blockIdx.x * 128, n0 = blockIdx.y * 128;
    const int bg = blockIdx.z, b = bg >> 4, gg = bg & 15;
    const int tid = threadIdx.x, lane = tid & 31, wid = tid >> 5;
    const int wm = wid & 1, wn = wid >> 1, g = lane >> 2, tg = lane & 3;

    const float*  Ab = p1 + (size_t)b * D1 * NTOT + gg * N1 + m0;
    const __half* Bg = &g_W1h[n0 + (tid >> 1)][(tid & 1) * 8];
    const int nb = tid >> 1, kb = (tid & 1) * 8;

    float acc[4][4][4] = {};
    float4 pa[2][2];
    uint4  pbh[2];
    #pragma unroll
    for (int s = 0; s < 2; s++) {
        #pragma unroll
        for (int v = 0; v < 2; v++)
            pa[s][v] = *(const float4*)(Ab + (size_t)(16 * s + (tid >> 5) + v * 8) * NTOT + (tid & 31) * 4);
        pbh[s] = *(const uint4*)(Bg + 16 * s);
    }
    #pragma unroll 2
    for (int s = 0; s < 8; s++) {
        const int set = s & 1;
        STAGE_STORE_A(As[set], pa[set]);
        *(uint4*)&Bs[set][nb][kb] = pbh[set];
        __syncthreads();
        if (s + 2 < 8) {
            const int kt = 16 * (s + 2);
            #pragma unroll
            for (int v = 0; v < 2; v++)
                pa[set][v] = *(const float4*)(Ab + (size_t)(kt + (tid >> 5) + v * 8) * NTOT + (tid & 31) * 4);
            pbh[set] = *(const uint4*)(Bg + kt);
        }
        compute_stage(As[set], Bs[set], acc, wm, wn, g, tg, lane);
    }

    // fp32 epilogue: interp(fp16 Y2t) + bias; fp16 store; BN1 partial stats.
    float ssum[4][2] = {}, sq[4][2] = {};
    #pragma unroll
    for (int i = 0; i < 4; i++) {
        const int rA = m0 + wm * 64 + i * 16 + g;
        const int rB = rA + 8;
        int   iA[3], iB[3];
        float wA[3], wB[3];
        #pragma unroll
        for (int k = 0; k < 3; k++) {
            iA[k] = g_idx[bg][rA][k]; wA[k] = g_w[bg][rA][k];
            iB[k] = g_idx[bg][rB][k]; wB[k] = g_w[bg][rB][k];
        }
        #pragma unroll
        for (int j = 0; j < 4; j++) {
            const int oh = (n0 + wn * 32 + j * 8) / 2 + tg;
            const int o  = 2 * oh;
            float c0 = acc[i][j][0], c1 = acc[i][j][1];
            float c2 = acc[i][j][2], c3 = acc[i][j][3];
            #pragma unroll
            for (int k = 0; k < 3; k++) {
                const float2 yA = __half22float2(g_Y2th[bg][iA[k]][oh]);
                c0 = fmaf(wA[k], yA.x, c0); c1 = fmaf(wA[k], yA.y, c1);
                const float2 yB = __half22float2(g_Y2th[bg][iB[k]][oh]);
                c2 = fmaf(wB[k], yB.x, c2); c3 = fmaf(wB[k], yB.y, c3);
            }
            const float2 bo = *(const float2*)(b1 + o);
            c0 += bo.x; c1 += bo.y; c2 += bo.x; c3 += bo.y;
            g_h1h[b][o][gg * N1 + rA]     = __float2half(c0);
            g_h1h[b][o + 1][gg * N1 + rA] = __float2half(c1);
            g_h1h[b][o][gg * N1 + rB]     = __float2half(c2);
            g_h1h[b][o + 1][gg * N1 + rB] = __float2half(c3);
            ssum[j][0] += c0 + c2; sq[j][0] += c0 * c0 + c2 * c2;
            ssum[j][1] += c1 + c3; sq[j][1] += c1 * c1 + c3 * c3;
        }
    }
    epilogue_stats(ssum, sq, 0, gg, n0, wn, lane, b * 64 + blockIdx.x * 2 + wm);
}

// ============================================================
// K4/K6: finish BN stats (deterministic tree over NSLOT partials).
// ============================================================
__global__ __launch_bounds__(NSLOT) void bnfinish_kernel(
    const float* __restrict__ gamma, const float* __restrict__ beta, int layer)
{
    const int c = blockIdx.x, gg = blockIdx.y, tid = threadIdx.x;
    __shared__ float rs[NSLOT], rq[NSLOT];
    rs[tid] = g_ps[layer][gg][c][tid];
    rq[tid] = g_pq[layer][gg][c][tid];
    __syncthreads();
    for (int off = NSLOT / 2; off; off >>= 1) {
        if (tid < off) { rs[tid] += rs[tid + off]; rq[tid] += rq[tid + off]; }
        __syncthreads();
    }
    if (tid == 0) {
        const float inv = 1.0f / (float)BN_CNT;
        const float mean = rs[0] * inv;
        const float var = rq[0] * inv - mean * mean;
        const float sc = gamma[c] * rsqrtf(var + 1e-5f);
        const float sh = beta[c] - mean * sc;
        if (layer == 0) { g_scale1[gg][c] = sc; g_shift1[gg][c] = sh; }
        else            { g_scale2[gg][c] = sc; g_shift2[gg][c] = sh; }
    }
}

// ============================================================
// K5: h2_pre = W2 @ relu(bn1(h1)) + b2 -> fp16 store + BN2 partials.
// A fp16 with BN1+ReLU in half2; B staged to smem from fp16 W2.
// grid = (32, 2, 32)
// ============================================================
__global__ __launch_bounds__(256, 2) void gemm2_mma(
    const float* __restrict__ b2)
{
    __shared__ __half As[2][16][136];
    __shared__ __half Bs[2][128][24];
    const int m0 = blockIdx.x * 128, n0 = blockIdx.y * 128;
    const int bg = blockIdx.z, b = bg >> 4, gg = bg & 15;
    const int tid = threadIdx.x, lane = tid & 31, wid = tid >> 5;
    const int wm = wid & 1, wn = wid >> 1, g = lane >> 2, tg = lane & 3;

    const __half* Abh = &g_h1h[b][0][gg * N1 + m0];
    const __half* Bg  = &g_W2h[n0 + (tid >> 1)][(tid & 1) * 8];
    const int nb = tid >> 1, kb = (tid & 1) * 8;

    float acc[4][4][4] = {};
    const int ka = tid >> 4, ma = (tid & 15) * 8;
    uint4 pha[2], pbh[2];
    __half2 psc[2], psh[2];
    #pragma unroll
    for (int s = 0; s < 2; s++) {
        const int c = 16 * s + ka;
        pha[s] = *(const uint4*)(Abh + (size_t)c * NTOT + ma);
        psc[s] = __float2half2_rn(g_scale1[gg][c]);
        psh[s] = __float2half2_rn(g_shift1[gg][c]);
        pbh[s] = *(const uint4*)(Bg + 16 * s);
    }
    const __half2 hz = __float2half2_rn(0.f);
    #pragma unroll 2
    for (int s = 0; s < 16; s++) {
        const int set = s & 1;
        // A: BN1 + ReLU in half2, store to smem
        {
            const __half2* hp = (const __half2*)&pha[set];
            uint4 st;
            __half2* sp = (__half2*)&st;
            #pragma unroll
            for (int u = 0; u < 4; u++)
                sp[u] = __hmax2(__hfma2(hp[u], psc[set], psh[set]), hz);
            *(uint4*)&As[set][ka][ma] = st;
        }
        *(uint4*)&Bs[set][nb][kb] = pbh[set];
        __syncthreads();
        if (s + 2 < 16) {
            const int c = 16 * (s + 2) + ka;
            pha[set] = *(const uint4*)(Abh + (size_t)c * NTOT + ma);
            psc[set] = __float2half2_rn(g_scale1[gg][c]);
            psh[set] = __float2half2_rn(g_shift1[gg][c]);
            pbh[set] = *(const uint4*)(Bg + 16 * (s + 2));
        }
        compute_stage(As[set], Bs[set], acc, wm, wn, g, tg, lane);
    }

    // Epilogue: +bias, fp16 store to g_h2h, BN2 partial stats.
    float ssum[4][2] = {}, sq[4][2] = {};
    #pragma unroll
    for (int i = 0; i < 4; i++) {
        const int rA = m0 + wm * 64 + i * 16 + g;
        const int rB = rA + 8;
        #pragma unroll
        for (int j = 0; j < 4; j++) {
            const int o = n0 + wn * 32 + j * 8 + 2 * tg;
            const float2 bo = *(const float2*)(b2 + o);
            const float c0 = acc[i][j][0] + bo.x;
            const float c1 = acc[i][j][1] + bo.y;
            const float c2 = acc[i][j][2] + bo.x;
            const float c3 = acc[i][j][3] + bo.y;
            g_h2h[b][o][gg * N1 + rA]     = __float2half(c0);
            g_h2h[b][o + 1][gg * N1 + rA] = __float2half(c1);
            g_h2h[b][o][gg * N1 + rB]     = __float2half(c2);
            g_h2h[b][o + 1][gg * N1 + rB] = __float2half(c3);
            ssum[j][0] += c0 + c2; sq[j][0] += c0 * c0 + c2 * c2;
            ssum[j][1] += c1 + c3; sq[j][1] += c1 * c1 + c3 * c3;
        }
    }
    epilogue_stats(ssum, sq, 1, gg, n0, wn, lane, b * 64 + blockIdx.x * 2 + wm);
}

// ============================================================
// K7: BN2 + ReLU: fp16 g_h2h -> fp32 d_out.
// ============================================================
__global__ __launch_bounds__(256) void bnfinal_kernel(float* __restrict__ out)
{
    const size_t f4 = (size_t)blockIdx.x * 256 + threadIdx.x;
    const size_t f = f4 * 4;
    const int o = (int)((f >> 16) & 255);
    const int g = (int)((f >> 12) & 15);
    const float sc = g_scale2[g][o];
    const float sh = g_shift2[g][o];
    const uint2 hraw = ((const uint2*)&g_h2h[0][0][0])[f4];
    const float2 f0 = __half22float2(*(const __half2*)&hraw.x);
    const float2 f1 = __half22float2(*(const __half2*)&hraw.y);
    float4 v;
    v.x = fmaxf(fmaf(f0.x, sc, sh), 0.f);
    v.y = fmaxf(fmaf(f0.y, sc, sh), 0.f);
    v.z = fmaxf(fmaf(f1.x, sc, sh), 0.f);
    v.w = fmaxf(fmaf(f1.y, sc, sh), 0.f);
    ((float4*)out)[f4] = v;
}

// ============================================================
extern "C" void kernel_launch(void* const* d_in, const int* in_sizes, int n_in,
                              void* d_out, int out_size)
{
    (void)in_sizes; (void)n_in; (void)out_size;
    const float* xyz1    = (const float*)d_in[0];
    const float* points1 = (const float*)d_in[1];
    const float* xyz2    = (const float*)d_in[3];
    const float* points2 = (const float*)d_in[4];
    const float* W1      = (const float*)d_in[6];
    const float* b1      = (const float*)d_in[7];
    const float* gamma1  = (const float*)d_in[8];
    const float* beta1   = (const float*)d_in[9];
    const float* W2      = (const float*)d_in[10];
    const float* b2      = (const float*)d_in[11];
    const float* gamma2  = (const float*)d_in[12];
    const float* beta2   = (const float*)d_in[13];
    float* out = (float*)d_out;

    prep_w<<<(C1 * INCH + C2 * C1 + 255) / 256, 256>>>(W1, W2);
    knn_kernel<<<dim3(N1 / 256, BB * GG), 256>>>(xyz1, xyz2);
    y2t_mma<<<dim3(S1 / 128, C1 / 128, BB * GG), 256>>>(points2);
    h1_mma<<<dim3(N1 / 128, C1 / 128, BB * GG), 256>>>(points1, b1);
    bnfinish_kernel<<<dim3(C1, GG), NSLOT>>>(gamma1, beta1, 0);
    gemm2_mma<<<dim3(N1 / 128, C2 / 128, BB * GG), 256>>>(b2);
    bnfinish_kernel<<<dim3(C2, GG), NSLOT>>>(gamma2, beta2, 1);
    bnfinal_kernel<<<(BB * C2 * NTOT) / 4 / 256, 256>>>(out);
}

// round 14
// speedup vs baseline: 1.1571x; 1.0047x over previous
#include <cuda_runtime.h>
#include <cuda_fp16.h>
#include <cstdint>

// Problem constants (fixed by setup_inputs)
#define BB 2
#define GG 16
#define N1 4096
#define S1 1024
#define NTOT 65536   // GG*N1
#define STOT 16384   // GG*S1
#define D1 128
#define D2 256
#define C1 256
#define C2 256
#define INCH 384
#define BN_CNT 8192  // BB*N1 samples per (segment, channel)
#define NSLOT 128    // BN partial slots per (segment, channel)

// -------- device scratch (no allocations allowed) --------
__device__ __half2 g_Y2th[BB * GG][S1][C1 / 2]; // 16.7 MB: (W1b @ p2)^T, fp16
__device__ int    g_idx[BB * GG][N1][3];
__device__ float  g_w[BB * GG][N1][3];
__device__ __half g_h1n[BB][NTOT][C1];         // 67 MB: layer-1 pre-act, POINT-major
__device__ __half g_h2h[BB][C2][NTOT];         // 67 MB: layer-2 pre-act (channel-major)
__device__ __half g_W1h[C1][INCH];             // fp16 weights (pre-converted)
__device__ __half g_W2h[C2][C1];
__device__ __half g_s1h[GG][C1];               // BN1 scale/shift as fp16 (for gemm2)
__device__ __half g_b1h[GG][C1];
__device__ float  g_ps[2][GG][C1][NSLOT];      // BN partial sums
__device__ float  g_pq[2][GG][C1][NSLOT];      // BN partial sum-of-squares
__device__ float  g_scale1[GG][C1];
__device__ float  g_shift1[GG][C1];
__device__ float  g_scale2[GG][C2];
__device__ float  g_shift2[GG][C2];

// -------- fp16 helpers --------
__device__ __forceinline__ uint32_t f2h2(float lo, float hi) {
    uint32_t d;
    asm("cvt.rn.f16x2.f32 %0, %1, %2;" : "=r"(d) : "f"(hi), "f"(lo));
    return d;
}

__device__ __forceinline__ void hmma4(float c[4], const uint32_t a[4],
                                      uint32_t b0, uint32_t b1) {
    asm volatile(
        "mma.sync.aligned.m16n8k16.row.col.f32.f16.f16.f32 "
        "{%0,%1,%2,%3},{%4,%5,%6,%7},{%8,%9},{%0,%1,%2,%3};"
        : "+f"(c[0]), "+f"(c[1]), "+f"(c[2]), "+f"(c[3])
        : "r"(a[0]), "r"(a[1]), "r"(a[2]), "r"(a[3]), "r"(b0), "r"(b1));
}

// A-fragment via ldmatrix.x4.trans from As[k][m] (half, pitch 136)
__device__ __forceinline__ void compute_stage(
    const __half (*As)[136], const __half (*Bs)[24],
    float acc[4][4][4], int wm, int wn, int g, int tg, int lane)
{
    const int q  = lane >> 3, r = lane & 7;
    const int mq = (q & 1) * 8;
    const int kq = (q >> 1) * 8;
    uint32_t af[4][4];
    #pragma unroll
    for (int i = 0; i < 4; i++) {
        const int m = wm * 64 + i * 16;
        uint32_t sa = (uint32_t)__cvta_generic_to_shared(&As[kq + r][m + mq]);
        asm volatile(
            "ldmatrix.sync.aligned.m8n8.x4.trans.shared.b16 {%0,%1,%2,%3}, [%4];"
            : "=r"(af[i][0]), "=r"(af[i][1]), "=r"(af[i][2]), "=r"(af[i][3])
            : "r"(sa));
    }
    #pragma unroll
    for (int j = 0; j < 4; j++) {
        const int n = wn * 32 + j * 8 + g;
        const uint32_t b0 = *(const uint32_t*)&Bs[n][2 * tg];
        const uint32_t b1 = *(const uint32_t*)&Bs[n][2 * tg + 8];
        #pragma unroll
        for (int i = 0; i < 4; i++)
            hmma4(acc[i][j], af[i], b0, b1);
    }
}

// A-fragment via NON-trans ldmatrix.x4 from As[m][k] (half, pitch 24).
// Lane L loads row m+(L&15), col (L>>4)*8 -> mats (m0k0,m8k0,m0k8,m8k8).
__device__ __forceinline__ void compute_stage_nt(
    const __half (*As)[24], const __half (*Bs)[24],
    float acc[4][4][4], int wm, int wn, int g, int tg, int lane)
{
    uint32_t af[4][4];
    #pragma unroll
    for (int i = 0; i < 4; i++) {
        const int m = wm * 64 + i * 16;
        uint32_t sa = (uint32_t)__cvta_generic_to_shared(
            &As[m + (lane & 15)][(lane >> 4) * 8]);
        asm volatile(
            "ldmatrix.sync.aligned.m8n8.x4.shared.b16 {%0,%1,%2,%3}, [%4];"
            : "=r"(af[i][0]), "=r"(af[i][1]), "=r"(af[i][2]), "=r"(af[i][3])
            : "r"(sa));
    }
    #pragma unroll
    for (int j = 0; j < 4; j++) {
        const int n = wn * 32 + j * 8 + g;
        const uint32_t b0 = *(const uint32_t*)&Bs[n][2 * tg];
        const uint32_t b1 = *(const uint32_t*)&Bs[n][2 * tg + 8];
        #pragma unroll
        for (int i = 0; i < 4; i++)
            hmma4(acc[i][j], af[i], b0, b1);
    }
}

// Per-thread BN partial reduction (old layout: channels j*8+2tg pairs).
__device__ __forceinline__ void epilogue_stats(
    float ssum[4][2], float sq[4][2], int layer, int gg, int n0,
    int wn, int lane, int slot)
{
    #pragma unroll
    for (int off = 4; off <= 16; off <<= 1) {
        #pragma unroll
        for (int j = 0; j < 4; j++) {
            ssum[j][0] += __shfl_xor_sync(0xffffffffu, ssum[j][0], off);
            ssum[j][1] += __shfl_xor_sync(0xffffffffu, ssum[j][1], off);
            sq[j][0]   += __shfl_xor_sync(0xffffffffu, sq[j][0], off);
            sq[j][1]   += __shfl_xor_sync(0xffffffffu, sq[j][1], off);
        }
    }
    if (lane < 4) {
        #pragma unroll
        for (int j = 0; j < 4; j++) {
            const int c = n0 + wn * 32 + j * 8 + 2 * lane;
            g_ps[layer][gg][c][slot]     = ssum[j][0];
            g_pq[layer][gg][c][slot]     = sq[j][0];
            g_ps[layer][gg][c + 1][slot] = ssum[j][1];
            g_pq[layer][gg][c + 1][slot] = sq[j][1];
        }
    }
}

// ============================================================
// K0: pre-convert weights to fp16 (runs once per launch, ~3 us).
// ============================================================
__global__ __launch_bounds__(256) void prep_w(
    const float* __restrict__ W1, const float* __restrict__ W2)
{
    const int t = blockIdx.x * 256 + threadIdx.x;
    if (t < C1 * INCH) (&g_W1h[0][0])[t] = __float2half(W1[t]);
    const int u = t - C1 * INCH;
    if (u >= 0 && u < C2 * C1) (&g_W2h[0][0])[u] = __float2half(W2[u]);
}

// ============================================================
// K1: 3-NN + inverse-distance weights (fp32, unchanged).
// ============================================================
__global__ __launch_bounds__(256) void knn_kernel(
    const float* __restrict__ xyz1, const float* __restrict__ xyz2)
{
    __shared__ float sx[S1], sy[S1], sz[S1];
    const int bg = blockIdx.y;
    const int b = bg >> 4, g = bg & 15;
    const float* x2 = xyz2 + (size_t)b * 3 * STOT + g * S1;
    for (int s = threadIdx.x; s < S1; s += 256) {
        sx[s] = x2[s];
        sy[s] = x2[STOT + s];
        sz[s] = x2[2 * STOT + s];
    }
    __syncthreads();

    const int n = blockIdx.x * 256 + threadIdx.x;
    const float* x1 = xyz1 + (size_t)b * 3 * NTOT + g * N1 + n;
    const float qx = x1[0], qy = x1[NTOT], qz = x1[2 * NTOT];

    float d0 = 3.4e38f, d1 = 3.4e38f, d2 = 3.4e38f;
    int i0 = 0, i1 = 0, i2 = 0;
    #pragma unroll 4
    for (int s = 0; s < S1; s++) {
        const float dx = qx - sx[s];
        const float dy = qy - sy[s];
        const float dz = qz - sz[s];
        const float d = fmaf(dx, dx, fmaf(dy, dy, dz * dz));
        if (d < d2) {
            if (d < d1) {
                if (d < d0) { d2 = d1; i2 = i1; d1 = d0; i1 = i0; d0 = d; i0 = s; }
                else        { d2 = d1; i2 = i1; d1 = d;  i1 = s; }
            } else          { d2 = d;  i2 = s; }
        }
    }
    float w0 = 1.0f / (d0 + 1e-8f);
    float w1 = 1.0f / (d1 + 1e-8f);
    float w2 = 1.0f / (d2 + 1e-8f);
    const float inv = 1.0f / (w0 + w1 + w2);
    g_idx[bg][n][0] = i0; g_idx[bg][n][1] = i1; g_idx[bg][n][2] = i2;
    g_w[bg][n][0] = w0 * inv; g_w[bg][n][1] = w1 * inv; g_w[bg][n][2] = w2 * inv;
}

// A staging (fp32 -> fp16): 256 threads move 16k x 128m per stage.
#define STAGE_STORE_A(Asb, PA)                                          \
    {                                                                   \
        _Pragma("unroll")                                               \
        for (int v = 0; v < 2; v++) {                                   \
            const int kaa = (tid >> 5) + v * 8, maa = (tid & 31) * 4;   \
            uint2 h;                                                    \
            h.x = f2h2(PA[v].x, PA[v].y);                               \
            h.y = f2h2(PA[v].z, PA[v].w);                               \
            *(uint2*)&Asb[kaa][maa] = h;                                \
        }                                                               \
    }

// ============================================================
// K2: Y2t = (W1b @ p2)^T  (fp16 MMA, K=256). grid = (8, 2, 32)
// ============================================================
__global__ __launch_bounds__(256, 2) void y2t_mma(
    const float* __restrict__ p2)
{
    __shared__ __half As[2][16][136];
    __shared__ __half Bs[2][128][24];
    const int m0 = blockIdx.x * 128, n0 = blockIdx.y * 128;
    const int bg = blockIdx.z, b = bg >> 4, gg = bg & 15;
    const int tid = threadIdx.x, lane = tid & 31, wid = tid >> 5;
    const int wm = wid & 1, wn = wid >> 1, g = lane >> 2, tg = lane & 3;

    const float*  Ab = p2 + (size_t)b * D2 * STOT + gg * S1 + m0;
    const __half* Bg = &g_W1h[n0 + (tid >> 1)][128 + (tid & 1) * 8];
    const int nb = tid >> 1, kb = (tid & 1) * 8;

    float acc[4][4][4] = {};
    float4 pa[2][2];
    uint4  pbh[2];
    #pragma unroll
    for (int s = 0; s < 2; s++) {
        #pragma unroll
        for (int v = 0; v < 2; v++)
            pa[s][v] = *(const float4*)(Ab + (size_t)(16 * s + (tid >> 5) + v * 8) * STOT + (tid & 31) * 4);
        pbh[s] = *(const uint4*)(Bg + 16 * s);
    }
    #pragma unroll 2
    for (int s = 0; s < 16; s++) {
        const int set = s & 1;
        STAGE_STORE_A(As[set], pa[set]);
        *(uint4*)&Bs[set][nb][kb] = pbh[set];
        __syncthreads();
        if (s + 2 < 16) {
            const int kt = 16 * (s + 2);
            #pragma unroll
            for (int v = 0; v < 2; v++)
                pa[set][v] = *(const float4*)(Ab + (size_t)(kt + (tid >> 5) + v * 8) * STOT + (tid & 31) * 4);
            pbh[set] = *(const uint4*)(Bg + kt);
        }
        compute_stage(As[set], Bs[set], acc, wm, wn, g, tg, lane);
    }
    #pragma unroll
    for (int i = 0; i < 4; i++) {
        const int s = m0 + wm * 64 + i * 16 + g;
        #pragma unroll
        for (int j = 0; j < 4; j++) {
            const int oh = (n0 + wn * 32 + j * 8) / 2 + tg;
            g_Y2th[bg][s][oh]     = __floats2half2_rn(acc[i][j][0], acc[i][j][1]);
            g_Y2th[bg][s + 8][oh] = __floats2half2_rn(acc[i][j][2], acc[i][j][3]);
        }
    }
}

// ============================================================
// K3: h1_pre = W1a @ p1 + interp(Y2t) + b1 -> fp16 POINT-major store
// + BN1 partials. Epilogue transposes acc via per-warp smem tile so
// each thread owns (1 row x 8 consecutive channels): coalesced gather
// (uint4) and coalesced stores (STG.128). grid = (32, 2, 32)
// ============================================================
__global__ __launch_bounds__(256, 2) void h1_mma(
    const float* __restrict__ p1, const float* __restrict__ b1)
{
    __shared__ __half As[2][16][136];
    __shared__ __half Bs[2][128][24];
    __shared__ float  Tep[8][16][36];   // per-warp transpose tile
    const int m0 = blockIdx.x * 128, n0 = blockIdx.y * 128;
    const int bg = blockIdx.z, b = bg >> 4, gg = bg & 15;
    const int tid = threadIdx.x, lane = tid & 31, wid = tid >> 5;
    const int wm = wid & 1, wn = wid >> 1, g = lane >> 2, tg = lane & 3;

    const float*  Ab = p1 + (size_t)b * D1 * NTOT + gg * N1 + m0;
    const __half* Bg = &g_W1h[n0 + (tid >> 1)][(tid & 1) * 8];
    const int nb = tid >> 1, kb = (tid & 1) * 8;

    float acc[4][4][4] = {};
    float4 pa[2][2];
    uint4  pbh[2];
    #pragma unroll
    for (int s = 0; s < 2; s++) {
        #pragma unroll
        for (int v = 0; v < 2; v++)
            pa[s][v] = *(const float4*)(Ab + (size_t)(16 * s + (tid >> 5) + v * 8) * NTOT + (tid & 31) * 4);
        pbh[s] = *(const uint4*)(Bg + 16 * s);
    }
    #pragma unroll 2
    for (int s = 0; s < 8; s++) {
        const int set = s & 1;
        STAGE_STORE_A(As[set], pa[set]);
        *(uint4*)&Bs[set][nb][kb] = pbh[set];
        __syncthreads();
        if (s + 2 < 8) {
            const int kt = 16 * (s + 2);
            #pragma unroll
            for (int v = 0; v < 2; v++)
                pa[set][v] = *(const float4*)(Ab + (size_t)(kt + (tid >> 5) + v * 8) * NTOT + (tid & 31) * 4);
            pbh[set] = *(const uint4*)(Bg + kt);
        }
        compute_stage(As[set], Bs[set], acc, wm, wn, g, tg, lane);
    }

    // ---- transposed epilogue ----
    const int chbase = n0 + wn * 32 + tg * 8;     // 8 consecutive channels
    const float4 bi0 = *(const float4*)(b1 + chbase);
    const float4 bi1 = *(const float4*)(b1 + chbase + 4);
    const float bias8[8] = {bi0.x, bi0.y, bi0.z, bi0.w, bi1.x, bi1.y, bi1.z, bi1.w};
    float ssum8[8] = {}, sq8[8] = {};
    const int ohb = chbase / 2;

    #pragma unroll
    for (int i = 0; i < 4; i++) {
        // stage this i's acc into the warp tile [16 rows][32 ch]
        #pragma unroll
        for (int j = 0; j < 4; j++) {
            Tep[wid][g][j * 8 + 2 * tg]         = acc[i][j][0];
            Tep[wid][g][j * 8 + 2 * tg + 1]     = acc[i][j][1];
            Tep[wid][8 + g][j * 8 + 2 * tg]     = acc[i][j][2];
            Tep[wid][8 + g][j * 8 + 2 * tg + 1] = acc[i][j][3];
        }
        __syncwarp();
        #pragma unroll
        for (int h = 0; h < 2; h++) {
            const int lrow = h * 8 + g;
            const int rG = m0 + wm * 64 + i * 16 + lrow;
            const float4 va = *(const float4*)&Tep[wid][lrow][tg * 8];
            const float4 vb = *(const float4*)&Tep[wid][lrow][tg * 8 + 4];
            float v[8] = {va.x, va.y, va.z, va.w, vb.x, vb.y, vb.z, vb.w};
            #pragma unroll
            for (int k = 0; k < 3; k++) {
                const int   si = g_idx[bg][rG][k];
                const float wk = g_w[bg][rG][k];
                const uint4 y  = *(const uint4*)&g_Y2th[bg][si][ohb];
                const __half2* yh = (const __half2*)&y;
                #pragma unroll
                for (int e = 0; e < 4; e++) {
                    const float2 f = __half22float2(yh[e]);
                    v[2 * e]     = fmaf(wk, f.x, v[2 * e]);
                    v[2 * e + 1] = fmaf(wk, f.y, v[2 * e + 1]);
                }
            }
            uint4 st;
            uint32_t* sp = (uint32_t*)&st;
            #pragma unroll
            for (int e = 0; e < 4; e++) {
                const float lo = v[2 * e] + bias8[2 * e];
                const float hi = v[2 * e + 1] + bias8[2 * e + 1];
                sp[e] = f2h2(lo, hi);
                ssum8[2 * e] += lo;     sq8[2 * e]     = fmaf(lo, lo, sq8[2 * e]);
                ssum8[2 * e + 1] += hi; sq8[2 * e + 1] = fmaf(hi, hi, sq8[2 * e + 1]);
            }
            *(uint4*)&g_h1n[b][gg * N1 + rG][chbase] = st;
        }
        __syncwarp();
    }
    // reduce over g (lanes tg+4g): xor 4,8,16
    #pragma unroll
    for (int off = 4; off <= 16; off <<= 1)
        #pragma unroll
        for (int e = 0; e < 8; e++) {
            ssum8[e] += __shfl_xor_sync(0xffffffffu, ssum8[e], off);
            sq8[e]   += __shfl_xor_sync(0xffffffffu, sq8[e], off);
        }
    if (lane < 4) {
        const int slot = b * 64 + blockIdx.x * 2 + wm;
        const int cb = n0 + wn * 32 + lane * 8;
        #pragma unroll
        for (int e = 0; e < 8; e++) {
            g_ps[0][gg][cb + e][slot] = ssum8[e];
            g_pq[0][gg][cb + e][slot] = sq8[e];
        }
    }
}

// ============================================================
// K4/K6: finish BN stats; layer 0 also emits fp16 scale/shift for gemm2.
// ============================================================
__global__ __launch_bounds__(NSLOT) void bnfinish_kernel(
    const float* __restrict__ gamma, const float* __restrict__ beta, int layer)
{
    const int c = blockIdx.x, gg = blockIdx.y, tid = threadIdx.x;
    __shared__ float rs[NSLOT], rq[NSLOT];
    rs[tid] = g_ps[layer][gg][c][tid];
    rq[tid] = g_pq[layer][gg][c][tid];
    __syncthreads();
    for (int off = NSLOT / 2; off; off >>= 1) {
        if (tid < off) { rs[tid] += rs[tid + off]; rq[tid] += rq[tid + off]; }
        __syncthreads();
    }
    if (tid == 0) {
        const float inv = 1.0f / (float)BN_CNT;
        const float mean = rs[0] * inv;
        const float var = rq[0] * inv - mean * mean;
        const float sc = gamma[c] * rsqrtf(var + 1e-5f);
        const float sh = beta[c] - mean * sc;
        if (layer == 0) {
            g_scale1[gg][c] = sc; g_shift1[gg][c] = sh;
            g_s1h[gg][c] = __float2half(sc);
            g_b1h[gg][c] = __float2half(sh);
        } else {
            g_scale2[gg][c] = sc; g_shift2[gg][c] = sh;
        }
    }
}

// ============================================================
// K5: h2_pre = W2 @ relu(bn1(h1)) + b2 -> fp16 store + BN2 partials.
// A from POINT-major g_h1n (As[m][k], non-trans ldmatrix); BN1+ReLU in
// half2 with per-channel fp16 scale/shift. grid = (32, 2, 32)
// ============================================================
__global__ __launch_bounds__(256, 2) void gemm2_mma(
    const float* __restrict__ b2)
{
    __shared__ __half As[2][128][24];   // [m][k]
    __shared__ __half Bs[2][128][24];   // [n][k]
    const int m0 = blockIdx.x * 128, n0 = blockIdx.y * 128;
    const int bg = blockIdx.z, b = bg >> 4, gg = bg & 15;
    const int tid = threadIdx.x, lane = tid & 31, wid = tid >> 5;
    const int wm = wid & 1, wn = wid >> 1, g = lane >> 2, tg = lane & 3;

    const int pA = tid >> 1, ckA = (tid & 1) * 8;
    const __half* Ag = &g_h1n[b][gg * N1 + m0 + pA][ckA];
    const __half* Bg = &g_W2h[n0 + (tid >> 1)][(tid & 1) * 8];
    const int nb = tid >> 1, kb = (tid & 1) * 8;

    float acc[4][4][4] = {};
    uint4 pha[2], pbh[2];
    #pragma unroll
    for (int s = 0; s < 2; s++) {
        pha[s] = *(const uint4*)(Ag + 16 * s);
        pbh[s] = *(const uint4*)(Bg + 16 * s);
    }
    const __half2 hz = __float2half2_rn(0.f);
    #pragma unroll 2
    for (int s = 0; s < 16; s++) {
        const int set = s & 1;
        // BN1 + ReLU on the 8 channels [16s+ckA, +8) in half2
        {
            const uint4 scv = *(const uint4*)&g_s1h[gg][16 * s + ckA];
            const uint4 shv = *(const uint4*)&g_b1h[gg][16 * s + ckA];
            const __half2* ap = (const __half2*)&pha[set];
            const __half2* scp = (const __half2*)&scv;
            const __half2* shp = (const __half2*)&shv;
            uint4 st;
            __half2* sp = (__half2*)&st;
            #pragma unroll
            for (int u = 0; u < 4; u++)
                sp[u] = __hmax2(__hfma2(ap[u], scp[u], shp[u]), hz);
            *(uint4*)&As[set][pA][ckA] = st;
        }
        *(uint4*)&Bs[set][nb][kb] = pbh[set];
        __syncthreads();
        if (s + 2 < 16) {
            pha[set] = *(const uint4*)(Ag + 16 * (s + 2));
            pbh[set] = *(const uint4*)(Bg + 16 * (s + 2));
        }
        compute_stage_nt(As[set], Bs[set], acc, wm, wn, g, tg, lane);
    }

    // Epilogue: +bias, fp16 store to g_h2h (channel-major), BN2 partials.
    float ssum[4][2] = {}, sq[4][2] = {};
    #pragma unroll
    for (int i = 0; i < 4; i++) {
        const int rA = m0 + wm * 64 + i * 16 + g;
        const int rB = rA + 8;
        #pragma unroll
        for (int j = 0; j < 4; j++) {
            const int o = n0 + wn * 32 + j * 8 + 2 * tg;
            const float2 bo = *(const float2*)(b2 + o);
            const float c0 = acc[i][j][0] + bo.x;
            const float c1 = acc[i][j][1] + bo.y;
            const float c2 = acc[i][j][2] + bo.x;
            const float c3 = acc[i][j][3] + bo.y;
            g_h2h[b][o][gg * N1 + rA]     = __float2half(c0);
            g_h2h[b][o + 1][gg * N1 + rA] = __float2half(c1);
            g_h2h[b][o][gg * N1 + rB]     = __float2half(c2);
            g_h2h[b][o + 1][gg * N1 + rB] = __float2half(c3);
            ssum[j][0] += c0 + c2; sq[j][0] += c0 * c0 + c2 * c2;
            ssum[j][1] += c1 + c3; sq[j][1] += c1 * c1 + c3 * c3;
        }
    }
    epilogue_stats(ssum, sq, 1, gg, n0, wn, lane, b * 64 + blockIdx.x * 2 + wm);
}

// ============================================================
// K7: BN2 + ReLU: fp16 g_h2h -> fp32 d_out.
// ============================================================
__global__ __launch_bounds__(256) void bnfinal_kernel(float* __restrict__ out)
{
    const size_t f4 = (size_t)blockIdx.x * 256 + threadIdx.x;
    const size_t f = f4 * 4;
    const int o = (int)((f >> 16) & 255);
    const int g = (int)((f >> 12) & 15);
    const float sc = g_scale2[g][o];
    const float sh = g_shift2[g][o];
    const uint2 hraw = ((const uint2*)&g_h2h[0][0][0])[f4];
    const float2 f0 = __half22float2(*(const __half2*)&hraw.x);
    const float2 f1 = __half22float2(*(const __half2*)&hraw.y);
    float4 v;
    v.x = fmaxf(fmaf(f0.x, sc, sh), 0.f);
    v.y = fmaxf(fmaf(f0.y, sc, sh), 0.f);
    v.z = fmaxf(fmaf(f1.x, sc, sh), 0.f);
    v.w = fmaxf(fmaf(f1.y, sc, sh), 0.f);
    ((float4*)out)[f4] = v;
}

// ============================================================
extern "C" void kernel_launch(void* const* d_in, const int* in_sizes, int n_in,
                              void* d_out, int out_size)
{
    (void)in_sizes; (void)n_in; (void)out_size;
    const float* xyz1    = (const float*)d_in[0];
    const float* points1 = (const float*)d_in[1];
    const float* xyz2    = (const float*)d_in[3];
    const float* points2 = (const float*)d_in[4];
    const float* W1      = (const float*)d_in[6];
    const float* b1      = (const float*)d_in[7];
    const float* gamma1  = (const float*)d_in[8];
    const float* beta1   = (const float*)d_in[9];
    const float* W2      = (const float*)d_in[10];
    const float* b2      = (const float*)d_in[11];
    const float* gamma2  = (const float*)d_in[12];
    const float* beta2   = (const float*)d_in[13];
    float* out = (float*)d_out;

    prep_w<<<(C1 * INCH + C2 * C1 + 255) / 256, 256>>>(W1, W2);
    knn_kernel<<<dim3(N1 / 256, BB * GG), 256>>>(xyz1, xyz2);
    y2t_mma<<<dim3(S1 / 128, C1 / 128, BB * GG), 256>>>(points2);
    h1_mma<<<dim3(N1 / 128, C1 / 128, BB * GG), 256>>>(points1, b1);
    bnfinish_kernel<<<dim3(C1, GG), NSLOT>>>(gamma1, beta1, 0);
    gemm2_mma<<<dim3(N1 / 128, C2 / 128, BB * GG), 256>>>(b2);
    bnfinish_kernel<<<dim3(C2, GG), NSLOT>>>(gamma2, beta2, 1);
    bnfinal_kernel<<<(BB * C2 * NTOT) / 4 / 256, 256>>>(out);
}

// round 15
// speedup vs baseline: 1.2063x; 1.0426x over previous
#include <cuda_runtime.h>
#include <cuda_fp16.h>
#include <cstdint>

// Problem constants (fixed by setup_inputs)
#define BB 2
#define GG 16
#define N1 4096
#define S1 1024
#define NTOT 65536   // GG*N1
#define STOT 16384   // GG*S1
#define D1 128
#define D2 256
#define C1 256
#define C2 256
#define INCH 384
#define BN_CNT 8192  // BB*N1 samples per (segment, channel)
#define NSLOT 128    // BN partial slots per (segment, channel)

// -------- device scratch (no allocations allowed) --------
__device__ __half2 g_Y2th[BB * GG][S1][C1 / 2]; // 16.7 MB: (W1b @ p2)^T, fp16
__device__ int    g_idx[BB * GG][N1][3];
__device__ float  g_w[BB * GG][N1][3];
__device__ __half g_h1h[BB][C1][NTOT];         // 67 MB: layer-1 pre-act, CHANNEL-major
__device__ __half g_h2h[BB][C2][NTOT];         // 67 MB: layer-2 pre-act, channel-major
__device__ __half g_W1h[C1][INCH];             // fp16 weights (pre-converted)
__device__ __half g_W2h[C2][C1];
__device__ float  g_ps[2][GG][C1][NSLOT];      // BN partial sums
__device__ float  g_pq[2][GG][C1][NSLOT];      // BN partial sum-of-squares
__device__ float  g_scale1[GG][C1];
__device__ float  g_shift1[GG][C1];
__device__ float  g_scale2[GG][C2];
__device__ float  g_shift2[GG][C2];

// -------- fp16 helpers --------
__device__ __forceinline__ uint32_t f2h2(float lo, float hi) {
    uint32_t d;
    asm("cvt.rn.f16x2.f32 %0, %1, %2;" : "=r"(d) : "f"(hi), "f"(lo));
    return d;
}

__device__ __forceinline__ void hmma4(float c[4], const uint32_t a[4],
                                      uint32_t b0, uint32_t b1) {
    asm volatile(
        "mma.sync.aligned.m16n8k16.row.col.f32.f16.f16.f32 "
        "{%0,%1,%2,%3},{%4,%5,%6,%7},{%8,%9},{%0,%1,%2,%3};"
        : "+f"(c[0]), "+f"(c[1]), "+f"(c[2]), "+f"(c[3])
        : "r"(a[0]), "r"(a[1]), "r"(a[2]), "r"(a[3]), "r"(b0), "r"(b1));
}

// A-fragment via ldmatrix.x4.trans from As[k][m] (half, pitch 136)
// B-fragment via LDS.32 from Bs[n][k] (half, pitch 24) — conflict-free.
__device__ __forceinline__ void compute_stage(
    const __half (*As)[136], const __half (*Bs)[24],
    float acc[4][4][4], int wm, int wn, int g, int tg, int lane)
{
    const int q  = lane >> 3, r = lane & 7;
    const int mq = (q & 1) * 8;
    const int kq = (q >> 1) * 8;
    uint32_t af[4][4];
    #pragma unroll
    for (int i = 0; i < 4; i++) {
        const int m = wm * 64 + i * 16;
        uint32_t sa = (uint32_t)__cvta_generic_to_shared(&As[kq + r][m + mq]);
        asm volatile(
            "ldmatrix.sync.aligned.m8n8.x4.trans.shared.b16 {%0,%1,%2,%3}, [%4];"
            : "=r"(af[i][0]), "=r"(af[i][1]), "=r"(af[i][2]), "=r"(af[i][3])
            : "r"(sa));
    }
    #pragma unroll
    for (int j = 0; j < 4; j++) {
        const int n = wn * 32 + j * 8 + g;
        const uint32_t b0 = *(const uint32_t*)&Bs[n][2 * tg];
        const uint32_t b1 = *(const uint32_t*)&Bs[n][2 * tg + 8];
        #pragma unroll
        for (int i = 0; i < 4; i++)
            hmma4(acc[i][j], af[i], b0, b1);
    }
}

// Per-thread BN partial reduction (channel-pair layout), for gemm2.
__device__ __forceinline__ void epilogue_stats(
    float ssum[4][2], float sq[4][2], int layer, int gg, int n0,
    int wn, int lane, int slot)
{
    #pragma unroll
    for (int off = 4; off <= 16; off <<= 1) {
        #pragma unroll
        for (int j = 0; j < 4; j++) {
            ssum[j][0] += __shfl_xor_sync(0xffffffffu, ssum[j][0], off);
            ssum[j][1] += __shfl_xor_sync(0xffffffffu, ssum[j][1], off);
            sq[j][0]   += __shfl_xor_sync(0xffffffffu, sq[j][0], off);
            sq[j][1]   += __shfl_xor_sync(0xffffffffu, sq[j][1], off);
        }
    }
    if (lane < 4) {
        #pragma unroll
        for (int j = 0; j < 4; j++) {
            const int c = n0 + wn * 32 + j * 8 + 2 * lane;
            g_ps[layer][gg][c][slot]     = ssum[j][0];
            g_pq[layer][gg][c][slot]     = sq[j][0];
            g_ps[layer][gg][c + 1][slot] = ssum[j][1];
            g_pq[layer][gg][c + 1][slot] = sq[j][1];
        }
    }
}

// ============================================================
// K0: pre-convert weights to fp16 (runs once per launch, ~3 us).
// ============================================================
__global__ __launch_bounds__(256) void prep_w(
    const float* __restrict__ W1, const float* __restrict__ W2)
{
    const int t = blockIdx.x * 256 + threadIdx.x;
    if (t < C1 * INCH) (&g_W1h[0][0])[t] = __float2half(W1[t]);
    const int u = t - C1 * INCH;
    if (u >= 0 && u < C2 * C1) (&g_W2h[0][0])[u] = __float2half(W2[u]);
}

// ============================================================
// K1: 3-NN + inverse-distance weights (fp32, unchanged).
// ============================================================
__global__ __launch_bounds__(256) void knn_kernel(
    const float* __restrict__ xyz1, const float* __restrict__ xyz2)
{
    __shared__ float sx[S1], sy[S1], sz[S1];
    const int bg = blockIdx.y;
    const int b = bg >> 4, g = bg & 15;
    const float* x2 = xyz2 + (size_t)b * 3 * STOT + g * S1;
    for (int s = threadIdx.x; s < S1; s += 256) {
        sx[s] = x2[s];
        sy[s] = x2[STOT + s];
        sz[s] = x2[2 * STOT + s];
    }
    __syncthreads();

    const int n = blockIdx.x * 256 + threadIdx.x;
    const float* x1 = xyz1 + (size_t)b * 3 * NTOT + g * N1 + n;
    const float qx = x1[0], qy = x1[NTOT], qz = x1[2 * NTOT];

    float d0 = 3.4e38f, d1 = 3.4e38f, d2 = 3.4e38f;
    int i0 = 0, i1 = 0, i2 = 0;
    #pragma unroll 4
    for (int s = 0; s < S1; s++) {
        const float dx = qx - sx[s];
        const float dy = qy - sy[s];
        const float dz = qz - sz[s];
        const float d = fmaf(dx, dx, fmaf(dy, dy, dz * dz));
        if (d < d2) {
            if (d < d1) {
                if (d < d0) { d2 = d1; i2 = i1; d1 = d0; i1 = i0; d0 = d; i0 = s; }
                else        { d2 = d1; i2 = i1; d1 = d;  i1 = s; }
            } else          { d2 = d;  i2 = s; }
        }
    }
    float w0 = 1.0f / (d0 + 1e-8f);
    float w1 = 1.0f / (d1 + 1e-8f);
    float w2 = 1.0f / (d2 + 1e-8f);
    const float inv = 1.0f / (w0 + w1 + w2);
    g_idx[bg][n][0] = i0; g_idx[bg][n][1] = i1; g_idx[bg][n][2] = i2;
    g_w[bg][n][0] = w0 * inv; g_w[bg][n][1] = w1 * inv; g_w[bg][n][2] = w2 * inv;
}

// A staging (fp32 -> fp16): 256 threads move 16k x 128m per stage.
#define STAGE_STORE_A(Asb, PA)                                          \
    {                                                                   \
        _Pragma("unroll")                                               \
        for (int v = 0; v < 2; v++) {                                   \
            const int kaa = (tid >> 5) + v * 8, maa = (tid & 31) * 4;   \
            uint2 h;                                                    \
            h.x = f2h2(PA[v].x, PA[v].y);                               \
            h.y = f2h2(PA[v].z, PA[v].w);                               \
            *(uint2*)&Asb[kaa][maa] = h;                                \
        }                                                               \
    }

// ============================================================
// K2: Y2t = (W1b @ p2)^T  (fp16 MMA, K=256). grid = (8, 2, 32)
// ============================================================
__global__ __launch_bounds__(256, 2) void y2t_mma(
    const float* __restrict__ p2)
{
    __shared__ __half As[2][16][136];
    __shared__ __half Bs[2][128][24];
    const int m0 = blockIdx.x * 128, n0 = blockIdx.y * 128;
    const int bg = blockIdx.z, b = bg >> 4, gg = bg & 15;
    const int tid = threadIdx.x, lane = tid & 31, wid = tid >> 5;
    const int wm = wid & 1, wn = wid >> 1, g = lane >> 2, tg = lane & 3;

    const float*  Ab = p2 + (size_t)b * D2 * STOT + gg * S1 + m0;
    const __half* Bg = &g_W1h[n0 + (tid >> 1)][128 + (tid & 1) * 8];
    const int nb = tid >> 1, kb = (tid & 1) * 8;

    float acc[4][4][4] = {};
    float4 pa[2][2];
    uint4  pbh[2];
    #pragma unroll
    for (int s = 0; s < 2; s++) {
        #pragma unroll
        for (int v = 0; v < 2; v++)
            pa[s][v] = *(const float4*)(Ab + (size_t)(16 * s + (tid >> 5) + v * 8) * STOT + (tid & 31) * 4);
        pbh[s] = *(const uint4*)(Bg + 16 * s);
    }
    #pragma unroll 2
    for (int s = 0; s < 16; s++) {
        const int set = s & 1;
        STAGE_STORE_A(As[set], pa[set]);
        *(uint4*)&Bs[set][nb][kb] = pbh[set];
        __syncthreads();
        if (s + 2 < 16) {
            const int kt = 16 * (s + 2);
            #pragma unroll
            for (int v = 0; v < 2; v++)
                pa[set][v] = *(const float4*)(Ab + (size_t)(kt + (tid >> 5) + v * 8) * STOT + (tid & 31) * 4);
            pbh[set] = *(const uint4*)(Bg + kt);
        }
        compute_stage(As[set], Bs[set], acc, wm, wn, g, tg, lane);
    }
    #pragma unroll
    for (int i = 0; i < 4; i++) {
        const int s = m0 + wm * 64 + i * 16 + g;
        #pragma unroll
        for (int j = 0; j < 4; j++) {
            const int oh = (n0 + wn * 32 + j * 8) / 2 + tg;
            g_Y2th[bg][s][oh]     = __floats2half2_rn(acc[i][j][0], acc[i][j][1]);
            g_Y2th[bg][s + 8][oh] = __floats2half2_rn(acc[i][j][2], acc[i][j][3]);
        }
    }
}

// ============================================================
// K3: h1_pre = W1a @ p1 + interp(Y2t) + b1 -> CHANNEL-major fp16 store
// + BN1 partials. Epilogue: acc -> Tep; gather/interp with per-thread
// (1 row x 8 ch) ownership (wide uint4 Y2t loads); write fp32 back to
// Tep; re-read per-channel columns -> 2 STG.128 per i into g_h1h.
// grid = (32, 2, 32)
// ============================================================
__global__ __launch_bounds__(256, 2) void h1_mma(
    const float* __restrict__ p1, const float* __restrict__ b1)
{
    __shared__ __half As[2][16][136];
    __shared__ __half Bs[2][128][24];
    __shared__ float  Tep[8][16][40];   // per-warp transpose tile (pitch 40 for 16B align)
    const int m0 = blockIdx.x * 128, n0 = blockIdx.y * 128;
    const int bg = blockIdx.z, b = bg >> 4, gg = bg & 15;
    const int tid = threadIdx.x, lane = tid & 31, wid = tid >> 5;
    const int wm = wid & 1, wn = wid >> 1, g = lane >> 2, tg = lane & 3;

    const float*  Ab = p1 + (size_t)b * D1 * NTOT + gg * N1 + m0;
    const __half* Bg = &g_W1h[n0 + (tid >> 1)][(tid & 1) * 8];
    const int nb = tid >> 1, kb = (tid & 1) * 8;

    float acc[4][4][4] = {};
    float4 pa[2][2];
    uint4  pbh[2];
    #pragma unroll
    for (int s = 0; s < 2; s++) {
        #pragma unroll
        for (int v = 0; v < 2; v++)
            pa[s][v] = *(const float4*)(Ab + (size_t)(16 * s + (tid >> 5) + v * 8) * NTOT + (tid & 31) * 4);
        pbh[s] = *(const uint4*)(Bg + 16 * s);
    }
    #pragma unroll 2
    for (int s = 0; s < 8; s++) {
        const int set = s & 1;
        STAGE_STORE_A(As[set], pa[set]);
        *(uint4*)&Bs[set][nb][kb] = pbh[set];
        __syncthreads();
        if (s + 2 < 8) {
            const int kt = 16 * (s + 2);
            #pragma unroll
            for (int v = 0; v < 2; v++)
                pa[set][v] = *(const float4*)(Ab + (size_t)(kt + (tid >> 5) + v * 8) * NTOT + (tid & 31) * 4);
            pbh[set] = *(const uint4*)(Bg + kt);
        }
        compute_stage(As[set], Bs[set], acc, wm, wn, g, tg, lane);
    }

    // ---- doubly-transposed epilogue ----
    const int chbase = n0 + wn * 32 + tg * 8;     // 8 consecutive channels (gather)
    const float4 bi0 = *(const float4*)(b1 + chbase);
    const float4 bi1 = *(const float4*)(b1 + chbase + 4);
    const float bias8[8] = {bi0.x, bi0.y, bi0.z, bi0.w, bi1.x, bi1.y, bi1.z, bi1.w};
    const int ohb = chbase / 2;
    const int myc = n0 + wn * 32 + lane;          // channel owned for store/stats
    float ssum = 0.f, ssq = 0.f;

    #pragma unroll
    for (int i = 0; i < 4; i++) {
        // (1) acc -> Tep
        #pragma unroll
        for (int j = 0; j < 4; j++) {
            Tep[wid][g][j * 8 + 2 * tg]         = acc[i][j][0];
            Tep[wid][g][j * 8 + 2 * tg + 1]     = acc[i][j][1];
            Tep[wid][8 + g][j * 8 + 2 * tg]     = acc[i][j][2];
            Tep[wid][8 + g][j * 8 + 2 * tg + 1] = acc[i][j][3];
        }
        __syncwarp();
        // (2) gather + interp + bias on (row, 8ch); write fp32 back in place
        #pragma unroll
        for (int h = 0; h < 2; h++) {
            const int lrow = h * 8 + g;
            const int rG = m0 + wm * 64 + i * 16 + lrow;
            const float4 va = *(const float4*)&Tep[wid][lrow][tg * 8];
            const float4 vb = *(const float4*)&Tep[wid][lrow][tg * 8 + 4];
            float v[8] = {va.x, va.y, va.z, va.w, vb.x, vb.y, vb.z, vb.w};
            #pragma unroll
            for (int k = 0; k < 3; k++) {
                const int   si = g_idx[bg][rG][k];
                const float wk = g_w[bg][rG][k];
                const uint4 y  = *(const uint4*)&g_Y2th[bg][si][ohb];
                const __half2* yh = (const __half2*)&y;
                #pragma unroll
                for (int e = 0; e < 4; e++) {
                    const float2 f = __half22float2(yh[e]);
                    v[2 * e]     = fmaf(wk, f.x, v[2 * e]);
                    v[2 * e + 1] = fmaf(wk, f.y, v[2 * e + 1]);
                }
            }
            #pragma unroll
            for (int e = 0; e < 8; e++) v[e] += bias8[e];
            *(float4*)&Tep[wid][lrow][tg * 8]     = make_float4(v[0], v[1], v[2], v[3]);
            *(float4*)&Tep[wid][lrow][tg * 8 + 4] = make_float4(v[4], v[5], v[6], v[7]);
        }
        __syncwarp();
        // (3) column read (my channel x 16 rows) -> 2 STG.128 + stats
        {
            const int rG0 = m0 + wm * 64 + i * 16;
            float vv[16];
            #pragma unroll
            for (int r = 0; r < 16; r++) vv[r] = Tep[wid][r][lane];
            uint4 st0, st1;
            uint32_t* s0 = (uint32_t*)&st0;
            uint32_t* s1 = (uint32_t*)&st1;
            #pragma unroll
            for (int e = 0; e < 4; e++) {
                s0[e] = f2h2(vv[2 * e], vv[2 * e + 1]);
                s1[e] = f2h2(vv[8 + 2 * e], vv[9 + 2 * e]);
            }
            *(uint4*)&g_h1h[b][myc][gg * N1 + rG0]     = st0;
            *(uint4*)&g_h1h[b][myc][gg * N1 + rG0 + 8] = st1;
            #pragma unroll
            for (int r = 0; r < 16; r++) {
                ssum += vv[r];
                ssq = fmaf(vv[r], vv[r], ssq);
            }
        }
        __syncwarp();
    }
    const int slot = b * 64 + blockIdx.x * 2 + wm;
    g_ps[0][gg][myc][slot] = ssum;
    g_pq[0][gg][myc][slot] = ssq;
}

// ============================================================
// K4/K6: finish BN stats (deterministic tree over NSLOT partials).
// ============================================================
__global__ __launch_bounds__(NSLOT) void bnfinish_kernel(
    const float* __restrict__ gamma, const float* __restrict__ beta, int layer)
{
    const int c = blockIdx.x, gg = blockIdx.y, tid = threadIdx.x;
    __shared__ float rs[NSLOT], rq[NSLOT];
    rs[tid] = g_ps[layer][gg][c][tid];
    rq[tid] = g_pq[layer][gg][c][tid];
    __syncthreads();
    for (int off = NSLOT / 2; off; off >>= 1) {
        if (tid < off) { rs[tid] += rs[tid + off]; rq[tid] += rq[tid + off]; }
        __syncthreads();
    }
    if (tid == 0) {
        const float inv = 1.0f / (float)BN_CNT;
        const float mean = rs[0] * inv;
        const float var = rq[0] * inv - mean * mean;
        const float sc = gamma[c] * rsqrtf(var + 1e-5f);
        const float sh = beta[c] - mean * sc;
        if (layer == 0) { g_scale1[gg][c] = sc; g_shift1[gg][c] = sh; }
        else            { g_scale2[gg][c] = sc; g_shift2[gg][c] = sh; }
    }
}

// ============================================================
// K5: h2_pre = W2 @ relu(bn1(h1)) + b2 -> fp16 store + BN2 partials.
// R13-measured form: channel-major A from g_h1h, k-major smem, trans
// ldmatrix; BN1+ReLU in half2. grid = (32, 2, 32)
// ============================================================
__global__ __launch_bounds__(256, 2) void gemm2_mma(
    const float* __restrict__ b2)
{
    __shared__ __half As[2][16][136];
    __shared__ __half Bs[2][128][24];
    const int m0 = blockIdx.x * 128, n0 = blockIdx.y * 128;
    const int bg = blockIdx.z, b = bg >> 4, gg = bg & 15;
    const int tid = threadIdx.x, lane = tid & 31, wid = tid >> 5;
    const int wm = wid & 1, wn = wid >> 1, g = lane >> 2, tg = lane & 3;

    const __half* Abh = &g_h1h[b][0][gg * N1 + m0];
    const __half* Bg  = &g_W2h[n0 + (tid >> 1)][(tid & 1) * 8];
    const int nb = tid >> 1, kb = (tid & 1) * 8;

    float acc[4][4][4] = {};
    const int ka = tid >> 4, ma = (tid & 15) * 8;
    uint4 pha[2], pbh[2];
    __half2 psc[2], psh[2];
    #pragma unroll
    for (int s = 0; s < 2; s++) {
        const int c = 16 * s + ka;
        pha[s] = *(const uint4*)(Abh + (size_t)c * NTOT + ma);
        psc[s] = __float2half2_rn(g_scale1[gg][c]);
        psh[s] = __float2half2_rn(g_shift1[gg][c]);
        pbh[s] = *(const uint4*)(Bg + 16 * s);
    }
    const __half2 hz = __float2half2_rn(0.f);
    #pragma unroll 2
    for (int s = 0; s < 16; s++) {
        const int set = s & 1;
        // A: BN1 + ReLU in half2, store to smem As[k][m]
        {
            const __half2* hp = (const __half2*)&pha[set];
            uint4 st;
            __half2* sp = (__half2*)&st;
            #pragma unroll
            for (int u = 0; u < 4; u++)
                sp[u] = __hmax2(__hfma2(hp[u], psc[set], psh[set]), hz);
            *(uint4*)&As[set][ka][ma] = st;
        }
        *(uint4*)&Bs[set][nb][kb] = pbh[set];
        __syncthreads();
        if (s + 2 < 16) {
            const int c = 16 * (s + 2) + ka;
            pha[set] = *(const uint4*)(Abh + (size_t)c * NTOT + ma);
            psc[set] = __float2half2_rn(g_scale1[gg][c]);
            psh[set] = __float2half2_rn(g_shift1[gg][c]);
            pbh[set] = *(const uint4*)(Bg + 16 * (s + 2));
        }
        compute_stage(As[set], Bs[set], acc, wm, wn, g, tg, lane);
    }

    // Epilogue: +bias, fp16 store to g_h2h (channel-major), BN2 partials.
    float ssum[4][2] = {}, sq[4][2] = {};
    #pragma unroll
    for (int i = 0; i < 4; i++) {
        const int rA = m0 + wm * 64 + i * 16 + g;
        const int rB = rA + 8;
        #pragma unroll
        for (int j = 0; j < 4; j++) {
            const int o = n0 + wn * 32 + j * 8 + 2 * tg;
            const float2 bo = *(const float2*)(b2 + o);
            const float c0 = acc[i][j][0] + bo.x;
            const float c1 = acc[i][j][1] + bo.y;
            const float c2 = acc[i][j][2] + bo.x;
            const float c3 = acc[i][j][3] + bo.y;
            g_h2h[b][o][gg * N1 + rA]     = __float2half(c0);
            g_h2h[b][o + 1][gg * N1 + rA] = __float2half(c1);
            g_h2h[b][o][gg * N1 + rB]     = __float2half(c2);
            g_h2h[b][o + 1][gg * N1 + rB] = __float2half(c3);
            ssum[j][0] += c0 + c2; sq[j][0] += c0 * c0 + c2 * c2;
            ssum[j][1] += c1 + c3; sq[j][1] += c1 * c1 + c3 * c3;
        }
    }
    epilogue_stats(ssum, sq, 1, gg, n0, wn, lane, b * 64 + blockIdx.x * 2 + wm);
}

// ============================================================
// K7: BN2 + ReLU: fp16 g_h2h -> fp32 d_out.
// ============================================================
__global__ __launch_bounds__(256) void bnfinal_kernel(float* __restrict__ out)
{
    const size_t f4 = (size_t)blockIdx.x * 256 + threadIdx.x;
    const size_t f = f4 * 4;
    const int o = (int)((f >> 16) & 255);
    const int g = (int)((f >> 12) & 15);
    const float sc = g_scale2[g][o];
    const float sh = g_shift2[g][o];
    const uint2 hraw = ((const uint2*)&g_h2h[0][0][0])[f4];
    const float2 f0 = __half22float2(*(const __half2*)&hraw.x);
    const float2 f1 = __half22float2(*(const __half2*)&hraw.y);
    float4 v;
    v.x = fmaxf(fmaf(f0.x, sc, sh), 0.f);
    v.y = fmaxf(fmaf(f0.y, sc, sh), 0.f);
    v.z = fmaxf(fmaf(f1.x, sc, sh), 0.f);
    v.w = fmaxf(fmaf(f1.y, sc, sh), 0.f);
    ((float4*)out)[f4] = v;
}

// ============================================================
extern "C" void kernel_launch(void* const* d_in, const int* in_sizes, int n_in,
                              void* d_out, int out_size)
{
    (void)in_sizes; (void)n_in; (void)out_size;
    const float* xyz1    = (const float*)d_in[0];
    const float* points1 = (const float*)d_in[1];
    const float* xyz2    = (const float*)d_in[3];
    const float* points2 = (const float*)d_in[4];
    const float* W1      = (const float*)d_in[6];
    const float* b1      = (const float*)d_in[7];
    const float* gamma1  = (const float*)d_in[8];
    const float* beta1   = (const float*)d_in[9];
    const float* W2      = (const float*)d_in[10];
    const float* b2      = (const float*)d_in[11];
    const float* gamma2  = (const float*)d_in[12];
    const float* beta2   = (const float*)d_in[13];
    float* out = (float*)d_out;

    prep_w<<<(C1 * INCH + C2 * C1 + 255) / 256, 256>>>(W1, W2);
    knn_kernel<<<dim3(N1 / 256, BB * GG), 256>>>(xyz1, xyz2);
    y2t_mma<<<dim3(S1 / 128, C1 / 128, BB * GG), 256>>>(points2);
    h1_mma<<<dim3(N1 / 128, C1 / 128, BB * GG), 256>>>(points1, b1);
    bnfinish_kernel<<<dim3(C1, GG), NSLOT>>>(gamma1, beta1, 0);
    gemm2_mma<<<dim3(N1 / 128, C2 / 128, BB * GG), 256>>>(b2);
    bnfinish_kernel<<<dim3(C2, GG), NSLOT>>>(gamma2, beta2, 1);
    bnfinal_kernel<<<(BB * C2 * NTOT) / 4 / 256, 256>>>(out);
}

// round 16
// speedup vs baseline: 1.2609x; 1.0452x over previous
#include <cuda_runtime.h>
#include <cuda_fp16.h>
#include <cstdint>

// Problem constants (fixed by setup_inputs)
#define BB 2
#define GG 16
#define N1 4096
#define S1 1024
#define NTOT 65536   // GG*N1
#define STOT 16384   // GG*S1
#define D1 128
#define D2 256
#define C1 256
#define C2 256
#define INCH 384
#define BN_CNT 8192  // BB*N1 samples per (segment, channel)
#define NSLOT 128    // BN partial slots per (segment, channel)

// -------- device scratch (no allocations allowed) --------
__device__ __half2 g_Y2th[BB * GG][S1][C1 / 2]; // 16.7 MB: (W1b @ p2)^T, fp16
__device__ float4 g_iw0[BB * GG][N1];          // (w0,w1,w2, bits(i0))
__device__ float2 g_iw1[BB * GG][N1];          // (bits(i1), bits(i2))
__device__ __half g_h1h[BB][C1][NTOT];         // 67 MB: layer-1 pre-act, CHANNEL-major
__device__ __half g_h2h[BB][C2][NTOT];         // 67 MB: layer-2 pre-act, channel-major
__device__ __half g_W1h[C1][INCH];             // fp16 weights (pre-converted)
__device__ __half g_W2h[C2][C1];
__device__ float  g_ps[2][GG][C1][NSLOT];      // BN partial sums
__device__ float  g_pq[2][GG][C1][NSLOT];      // BN partial sum-of-squares
__device__ float  g_scale1[GG][C1];
__device__ float  g_shift1[GG][C1];
__device__ float  g_scale2[GG][C2];
__device__ float  g_shift2[GG][C2];

// -------- fp16 helpers --------
__device__ __forceinline__ uint32_t f2h2(float lo, float hi) {
    uint32_t d;
    asm("cvt.rn.f16x2.f32 %0, %1, %2;" : "=r"(d) : "f"(hi), "f"(lo));
    return d;
}

__device__ __forceinline__ void hmma4(float c[4], const uint32_t a[4],
                                      uint32_t b0, uint32_t b1) {
    asm volatile(
        "mma.sync.aligned.m16n8k16.row.col.f32.f16.f16.f32 "
        "{%0,%1,%2,%3},{%4,%5,%6,%7},{%8,%9},{%0,%1,%2,%3};"
        : "+f"(c[0]), "+f"(c[1]), "+f"(c[2]), "+f"(c[3])
        : "r"(a[0]), "r"(a[1]), "r"(a[2]), "r"(a[3]), "r"(b0), "r"(b1));
}

// A-fragment via ldmatrix.x4.trans from As[k][m] (half, pitch 136)
// B-fragment via LDS.32 from Bs[n][k] (half, pitch 24) — conflict-free.
__device__ __forceinline__ void compute_stage(
    const __half (*As)[136], const __half (*Bs)[24],
    float acc[4][4][4], int wm, int wn, int g, int tg, int lane)
{
    const int q  = lane >> 3, r = lane & 7;
    const int mq = (q & 1) * 8;
    const int kq = (q >> 1) * 8;
    uint32_t af[4][4];
    #pragma unroll
    for (int i = 0; i < 4; i++) {
        const int m = wm * 64 + i * 16;
        uint32_t sa = (uint32_t)__cvta_generic_to_shared(&As[kq + r][m + mq]);
        asm volatile(
            "ldmatrix.sync.aligned.m8n8.x4.trans.shared.b16 {%0,%1,%2,%3}, [%4];"
            : "=r"(af[i][0]), "=r"(af[i][1]), "=r"(af[i][2]), "=r"(af[i][3])
            : "r"(sa));
    }
    #pragma unroll
    for (int j = 0; j < 4; j++) {
        const int n = wn * 32 + j * 8 + g;
        const uint32_t b0 = *(const uint32_t*)&Bs[n][2 * tg];
        const uint32_t b1 = *(const uint32_t*)&Bs[n][2 * tg + 8];
        #pragma unroll
        for (int i = 0; i < 4; i++)
            hmma4(acc[i][j], af[i], b0, b1);
    }
}

// Per-thread BN partial reduction (channel-pair layout), for gemm2.
__device__ __forceinline__ void epilogue_stats(
    float ssum[4][2], float sq[4][2], int layer, int gg, int n0,
    int wn, int lane, int slot)
{
    #pragma unroll
    for (int off = 4; off <= 16; off <<= 1) {
        #pragma unroll
        for (int j = 0; j < 4; j++) {
            ssum[j][0] += __shfl_xor_sync(0xffffffffu, ssum[j][0], off);
            ssum[j][1] += __shfl_xor_sync(0xffffffffu, ssum[j][1], off);
            sq[j][0]   += __shfl_xor_sync(0xffffffffu, sq[j][0], off);
            sq[j][1]   += __shfl_xor_sync(0xffffffffu, sq[j][1], off);
        }
    }
    if (lane < 4) {
        #pragma unroll
        for (int j = 0; j < 4; j++) {
            const int c = n0 + wn * 32 + j * 8 + 2 * lane;
            g_ps[layer][gg][c][slot]     = ssum[j][0];
            g_pq[layer][gg][c][slot]     = sq[j][0];
            g_ps[layer][gg][c + 1][slot] = ssum[j][1];
            g_pq[layer][gg][c + 1][slot] = sq[j][1];
        }
    }
}

// ============================================================
// K0: pre-convert weights to fp16 (runs once per launch, ~3 us).
// ============================================================
__global__ __launch_bounds__(256) void prep_w(
    const float* __restrict__ W1, const float* __restrict__ W2)
{
    const int t = blockIdx.x * 256 + threadIdx.x;
    if (t < C1 * INCH) (&g_W1h[0][0])[t] = __float2half(W1[t]);
    const int u = t - C1 * INCH;
    if (u >= 0 && u < C2 * C1) (&g_W2h[0][0])[u] = __float2half(W2[u]);
}

// ============================================================
// K1: 3-NN + inverse-distance weights.
// Dot-product form: score = 0.5|s|^2 - q.s (same ordering as distance);
// true d for the 3 winners reconstructed as max(2*score + |q|^2, 0).
// Sources in smem as float4 (x,y,z,0.5|s|^2): 1 LDS.128 + 3 FFMA / source.
// ============================================================
__global__ __launch_bounds__(256) void knn_kernel(
    const float* __restrict__ xyz1, const float* __restrict__ xyz2)
{
    __shared__ float4 sp[S1];
    const int bg = blockIdx.y;
    const int b = bg >> 4, g = bg & 15;
    const float* x2 = xyz2 + (size_t)b * 3 * STOT + g * S1;
    for (int s = threadIdx.x; s < S1; s += 256) {
        const float x = x2[s], y = x2[STOT + s], z = x2[2 * STOT + s];
        sp[s] = make_float4(x, y, z, 0.5f * fmaf(x, x, fmaf(y, y, z * z)));
    }
    __syncthreads();

    const int n = blockIdx.x * 256 + threadIdx.x;
    const float* x1 = xyz1 + (size_t)b * 3 * NTOT + g * N1 + n;
    const float qx = x1[0], qy = x1[NTOT], qz = x1[2 * NTOT];
    const float qn = fmaf(qx, qx, fmaf(qy, qy, qz * qz));

    float s0 = 3.4e38f, s1 = 3.4e38f, s2 = 3.4e38f;
    int i0 = 0, i1 = 0, i2 = 0;
    #pragma unroll 8
    for (int s = 0; s < S1; s++) {
        const float4 v = sp[s];
        float sc = v.w;
        sc = fmaf(-qx, v.x, sc);
        sc = fmaf(-qy, v.y, sc);
        sc = fmaf(-qz, v.z, sc);
        if (sc < s2) {
            if (sc < s1) {
                if (sc < s0) { s2 = s1; i2 = i1; s1 = s0; i1 = i0; s0 = sc; i0 = s; }
                else         { s2 = s1; i2 = i1; s1 = sc; i1 = s; }
            } else           { s2 = sc; i2 = s; }
        }
    }
    const float d0 = fmaxf(fmaf(2.f, s0, qn), 0.f);
    const float d1 = fmaxf(fmaf(2.f, s1, qn), 0.f);
    const float d2 = fmaxf(fmaf(2.f, s2, qn), 0.f);
    float w0 = 1.0f / (d0 + 1e-8f);
    float w1 = 1.0f / (d1 + 1e-8f);
    float w2 = 1.0f / (d2 + 1e-8f);
    const float inv = 1.0f / (w0 + w1 + w2);
    g_iw0[bg][n] = make_float4(w0 * inv, w1 * inv, w2 * inv, __int_as_float(i0));
    g_iw1[bg][n] = make_float2(__int_as_float(i1), __int_as_float(i2));
}

// A staging (fp32 -> fp16): 256 threads move 16k x 128m per stage.
#define STAGE_STORE_A(Asb, PA)                                          \
    {                                                                   \
        _Pragma("unroll")                                               \
        for (int v = 0; v < 2; v++) {                                   \
            const int kaa = (tid >> 5) + v * 8, maa = (tid & 31) * 4;   \
            uint2 h;                                                    \
            h.x = f2h2(PA[v].x, PA[v].y);                               \
            h.y = f2h2(PA[v].z, PA[v].w);                               \
            *(uint2*)&Asb[kaa][maa] = h;                                \
        }                                                               \
    }

// ============================================================
// K2: Y2t = (W1b @ p2)^T  (fp16 MMA, K=256). grid = (8, 2, 32)
// ============================================================
__global__ __launch_bounds__(256, 2) void y2t_mma(
    const float* __restrict__ p2)
{
    __shared__ __half As[2][16][136];
    __shared__ __half Bs[2][128][24];
    const int m0 = blockIdx.x * 128, n0 = blockIdx.y * 128;
    const int bg = blockIdx.z, b = bg >> 4, gg = bg & 15;
    const int tid = threadIdx.x, lane = tid & 31, wid = tid >> 5;
    const int wm = wid & 1, wn = wid >> 1, g = lane >> 2, tg = lane & 3;

    const float*  Ab = p2 + (size_t)b * D2 * STOT + gg * S1 + m0;
    const __half* Bg = &g_W1h[n0 + (tid >> 1)][128 + (tid & 1) * 8];
    const int nb = tid >> 1, kb = (tid & 1) * 8;

    float acc[4][4][4] = {};
    float4 pa[2][2];
    uint4  pbh[2];
    #pragma unroll
    for (int s = 0; s < 2; s++) {
        #pragma unroll
        for (int v = 0; v < 2; v++)
            pa[s][v] = *(const float4*)(Ab + (size_t)(16 * s + (tid >> 5) + v * 8) * STOT + (tid & 31) * 4);
        pbh[s] = *(const uint4*)(Bg + 16 * s);
    }
    #pragma unroll 2
    for (int s = 0; s < 16; s++) {
        const int set = s & 1;
        STAGE_STORE_A(As[set], pa[set]);
        *(uint4*)&Bs[set][nb][kb] = pbh[set];
        __syncthreads();
        if (s + 2 < 16) {
            const int kt = 16 * (s + 2);
            #pragma unroll
            for (int v = 0; v < 2; v++)
                pa[set][v] = *(const float4*)(Ab + (size_t)(kt + (tid >> 5) + v * 8) * STOT + (tid & 31) * 4);
            pbh[set] = *(const uint4*)(Bg + kt);
        }
        compute_stage(As[set], Bs[set], acc, wm, wn, g, tg, lane);
    }
    #pragma unroll
    for (int i = 0; i < 4; i++) {
        const int s = m0 + wm * 64 + i * 16 + g;
        #pragma unroll
        for (int j = 0; j < 4; j++) {
            const int oh = (n0 + wn * 32 + j * 8) / 2 + tg;
            g_Y2th[bg][s][oh]     = __floats2half2_rn(acc[i][j][0], acc[i][j][1]);
            g_Y2th[bg][s + 8][oh] = __floats2half2_rn(acc[i][j][2], acc[i][j][3]);
        }
    }
}

// ============================================================
// K3: h1_pre = W1a @ p1 + interp(Y2t) + b1 -> CHANNEL-major fp16 store
// + BN1 partials. Doubly-transposed epilogue (wide gather + wide store).
// grid = (32, 2, 32)
// ============================================================
__global__ __launch_bounds__(256, 2) void h1_mma(
    const float* __restrict__ p1, const float* __restrict__ b1)
{
    __shared__ __half As[2][16][136];
    __shared__ __half Bs[2][128][24];
    __shared__ float  Tep[8][16][40];   // per-warp transpose tile
    const int m0 = blockIdx.x * 128, n0 = blockIdx.y * 128;
    const int bg = blockIdx.z, b = bg >> 4, gg = bg & 15;
    const int tid = threadIdx.x, lane = tid & 31, wid = tid >> 5;
    const int wm = wid & 1, wn = wid >> 1, g = lane >> 2, tg = lane & 3;

    const float*  Ab = p1 + (size_t)b * D1 * NTOT + gg * N1 + m0;
    const __half* Bg = &g_W1h[n0 + (tid >> 1)][(tid & 1) * 8];
    const int nb = tid >> 1, kb = (tid & 1) * 8;

    float acc[4][4][4] = {};
    float4 pa[2][2];
    uint4  pbh[2];
    #pragma unroll
    for (int s = 0; s < 2; s++) {
        #pragma unroll
        for (int v = 0; v < 2; v++)
            pa[s][v] = *(const float4*)(Ab + (size_t)(16 * s + (tid >> 5) + v * 8) * NTOT + (tid & 31) * 4);
        pbh[s] = *(const uint4*)(Bg + 16 * s);
    }
    #pragma unroll 2
    for (int s = 0; s < 8; s++) {
        const int set = s & 1;
        STAGE_STORE_A(As[set], pa[set]);
        *(uint4*)&Bs[set][nb][kb] = pbh[set];
        __syncthreads();
        if (s + 2 < 8) {
            const int kt = 16 * (s + 2);
            #pragma unroll
            for (int v = 0; v < 2; v++)
                pa[set][v] = *(const float4*)(Ab + (size_t)(kt + (tid >> 5) + v * 8) * NTOT + (tid & 31) * 4);
            pbh[set] = *(const uint4*)(Bg + kt);
        }
        compute_stage(As[set], Bs[set], acc, wm, wn, g, tg, lane);
    }

    // ---- doubly-transposed epilogue ----
    const int chbase = n0 + wn * 32 + tg * 8;     // 8 consecutive channels (gather)
    const float4 bi0 = *(const float4*)(b1 + chbase);
    const float4 bi1 = *(const float4*)(b1 + chbase + 4);
    const float bias8[8] = {bi0.x, bi0.y, bi0.z, bi0.w, bi1.x, bi1.y, bi1.z, bi1.w};
    const int ohb = chbase / 2;
    const int myc = n0 + wn * 32 + lane;          // channel owned for store/stats
    float ssum = 0.f, ssq = 0.f;

    #pragma unroll
    for (int i = 0; i < 4; i++) {
        // (1) acc -> Tep
        #pragma unroll
        for (int j = 0; j < 4; j++) {
            Tep[wid][g][j * 8 + 2 * tg]         = acc[i][j][0];
            Tep[wid][g][j * 8 + 2 * tg + 1]     = acc[i][j][1];
            Tep[wid][8 + g][j * 8 + 2 * tg]     = acc[i][j][2];
            Tep[wid][8 + g][j * 8 + 2 * tg + 1] = acc[i][j][3];
        }
        __syncwarp();
        // (2) gather + interp + bias on (row, 8ch); write fp32 back in place
        #pragma unroll
        for (int h = 0; h < 2; h++) {
            const int lrow = h * 8 + g;
            const int rG = m0 + wm * 64 + i * 16 + lrow;
            const float4 iw0 = g_iw0[bg][rG];
            const float2 iw1 = g_iw1[bg][rG];
            const int   sidx[3] = {__float_as_int(iw0.w), __float_as_int(iw1.x),
                                   __float_as_int(iw1.y)};
            const float wk3[3]  = {iw0.x, iw0.y, iw0.z};
            const float4 va = *(const float4*)&Tep[wid][lrow][tg * 8];
            const float4 vb = *(const float4*)&Tep[wid][lrow][tg * 8 + 4];
            float v[8] = {va.x, va.y, va.z, va.w, vb.x, vb.y, vb.z, vb.w};
            #pragma unroll
            for (int k = 0; k < 3; k++) {
                const uint4 y  = *(const uint4*)&g_Y2th[bg][sidx[k]][ohb];
                const __half2* yh = (const __half2*)&y;
                const float wk = wk3[k];
                #pragma unroll
                for (int e = 0; e < 4; e++) {
                    const float2 f = __half22float2(yh[e]);
                    v[2 * e]     = fmaf(wk, f.x, v[2 * e]);
                    v[2 * e + 1] = fmaf(wk, f.y, v[2 * e + 1]);
                }
            }
            #pragma unroll
            for (int e = 0; e < 8; e++) v[e] += bias8[e];
            *(float4*)&Tep[wid][lrow][tg * 8]     = make_float4(v[0], v[1], v[2], v[3]);
            *(float4*)&Tep[wid][lrow][tg * 8 + 4] = make_float4(v[4], v[5], v[6], v[7]);
        }
        __syncwarp();
        // (3) column read (my channel x 16 rows) -> 2 STG.128 + stats
        {
            const int rG0 = m0 + wm * 64 + i * 16;
            float vv[16];
            #pragma unroll
            for (int r = 0; r < 16; r++) vv[r] = Tep[wid][r][lane];
            uint4 st0, st1;
            uint32_t* s0 = (uint32_t*)&st0;
            uint32_t* s1 = (uint32_t*)&st1;
            #pragma unroll
            for (int e = 0; e < 4; e++) {
                s0[e] = f2h2(vv[2 * e], vv[2 * e + 1]);
                s1[e] = f2h2(vv[8 + 2 * e], vv[9 + 2 * e]);
            }
            *(uint4*)&g_h1h[b][myc][gg * N1 + rG0]     = st0;
            *(uint4*)&g_h1h[b][myc][gg * N1 + rG0 + 8] = st1;
            #pragma unroll
            for (int r = 0; r < 16; r++) {
                ssum += vv[r];
                ssq = fmaf(vv[r], vv[r], ssq);
            }
        }
        __syncwarp();
    }
    const int slot = b * 64 + blockIdx.x * 2 + wm;
    g_ps[0][gg][myc][slot] = ssum;
    g_pq[0][gg][myc][slot] = ssq;
}

// ============================================================
// K4/K6: finish BN stats (deterministic tree over NSLOT partials).
// ============================================================
__global__ __launch_bounds__(NSLOT) void bnfinish_kernel(
    const float* __restrict__ gamma, const float* __restrict__ beta, int layer)
{
    const int c = blockIdx.x, gg = blockIdx.y, tid = threadIdx.x;
    __shared__ float rs[NSLOT], rq[NSLOT];
    rs[tid] = g_ps[layer][gg][c][tid];
    rq[tid] = g_pq[layer][gg][c][tid];
    __syncthreads();
    for (int off = NSLOT / 2; off; off >>= 1) {
        if (tid < off) { rs[tid] += rs[tid + off]; rq[tid] += rq[tid + off]; }
        __syncthreads();
    }
    if (tid == 0) {
        const float inv = 1.0f / (float)BN_CNT;
        const float mean = rs[0] * inv;
        const float var = rq[0] * inv - mean * mean;
        const float sc = gamma[c] * rsqrtf(var + 1e-5f);
        const float sh = beta[c] - mean * sc;
        if (layer == 0) { g_scale1[gg][c] = sc; g_shift1[gg][c] = sh; }
        else            { g_scale2[gg][c] = sc; g_shift2[gg][c] = sh; }
    }
}

// ============================================================
// K5: h2_pre = W2 @ relu(bn1(h1)) + b2 -> fp16 store + BN2 partials.
// Channel-major A from g_h1h, k-major smem, trans ldmatrix; BN1+ReLU
// in half2. grid = (32, 2, 32)
// ============================================================
__global__ __launch_bounds__(256, 2) void gemm2_mma(
    const float* __restrict__ b2)
{
    __shared__ __half As[2][16][136];
    __shared__ __half Bs[2][128][24];
    const int m0 = blockIdx.x * 128, n0 = blockIdx.y * 128;
    const int bg = blockIdx.z, b = bg >> 4, gg = bg & 15;
    const int tid = threadIdx.x, lane = tid & 31, wid = tid >> 5;
    const int wm = wid & 1, wn = wid >> 1, g = lane >> 2, tg = lane & 3;

    const __half* Abh = &g_h1h[b][0][gg * N1 + m0];
    const __half* Bg  = &g_W2h[n0 + (tid >> 1)][(tid & 1) * 8];
    const int nb = tid >> 1, kb = (tid & 1) * 8;

    float acc[4][4][4] = {};
    const int ka = tid >> 4, ma = (tid & 15) * 8;
    uint4 pha[2], pbh[2];
    __half2 psc[2], psh[2];
    #pragma unroll
    for (int s = 0; s < 2; s++) {
        const int c = 16 * s + ka;
        pha[s] = *(const uint4*)(Abh + (size_t)c * NTOT + ma);
        psc[s] = __float2half2_rn(g_scale1[gg][c]);
        psh[s] = __float2half2_rn(g_shift1[gg][c]);
        pbh[s] = *(const uint4*)(Bg + 16 * s);
    }
    const __half2 hz = __float2half2_rn(0.f);
    #pragma unroll 2
    for (int s = 0; s < 16; s++) {
        const int set = s & 1;
        // A: BN1 + ReLU in half2, store to smem As[k][m]
        {
            const __half2* hp = (const __half2*)&pha[set];
            uint4 st;
            __half2* sp = (__half2*)&st;
            #pragma unroll
            for (int u = 0; u < 4; u++)
                sp[u] = __hmax2(__hfma2(hp[u], psc[set], psh[set]), hz);
            *(uint4*)&As[set][ka][ma] = st;
        }
        *(uint4*)&Bs[set][nb][kb] = pbh[set];
        __syncthreads();
        if (s + 2 < 16) {
            const int c = 16 * (s + 2) + ka;
            pha[set] = *(const uint4*)(Abh + (size_t)c * NTOT + ma);
            psc[set] = __float2half2_rn(g_scale1[gg][c]);
            psh[set] = __float2half2_rn(g_shift1[gg][c]);
            pbh[set] = *(const uint4*)(Bg + 16 * (s + 2));
        }
        compute_stage(As[set], Bs[set], acc, wm, wn, g, tg, lane);
    }

    // Epilogue: +bias, fp16 store to g_h2h (channel-major), BN2 partials.
    float ssum[4][2] = {}, sq[4][2] = {};
    #pragma unroll
    for (int i = 0; i < 4; i++) {
        const int rA = m0 + wm * 64 + i * 16 + g;
        const int rB = rA + 8;
        #pragma unroll
        for (int j = 0; j < 4; j++) {
            const int o = n0 + wn * 32 + j * 8 + 2 * tg;
            const float2 bo = *(const float2*)(b2 + o);
            const float c0 = acc[i][j][0] + bo.x;
            const float c1 = acc[i][j][1] + bo.y;
            const float c2 = acc[i][j][2] + bo.x;
            const float c3 = acc[i][j][3] + bo.y;
            g_h2h[b][o][gg * N1 + rA]     = __float2half(c0);
            g_h2h[b][o + 1][gg * N1 + rA] = __float2half(c1);
            g_h2h[b][o][gg * N1 + rB]     = __float2half(c2);
            g_h2h[b][o + 1][gg * N1 + rB] = __float2half(c3);
            ssum[j][0] += c0 + c2; sq[j][0] += c0 * c0 + c2 * c2;
            ssum[j][1] += c1 + c3; sq[j][1] += c1 * c1 + c3 * c3;
        }
    }
    epilogue_stats(ssum, sq, 1, gg, n0, wn, lane, b * 64 + blockIdx.x * 2 + wm);
}

// ============================================================
// K7: BN2 + ReLU: fp16 g_h2h -> fp32 d_out.
// ============================================================
__global__ __launch_bounds__(256) void bnfinal_kernel(float* __restrict__ out)
{
    const size_t f4 = (size_t)blockIdx.x * 256 + threadIdx.x;
    const size_t f = f4 * 4;
    const int o = (int)((f >> 16) & 255);
    const int g = (int)((f >> 12) & 15);
    const float sc = g_scale2[g][o];
    const float sh = g_shift2[g][o];
    const uint2 hraw = ((const uint2*)&g_h2h[0][0][0])[f4];
    const float2 f0 = __half22float2(*(const __half2*)&hraw.x);
    const float2 f1 = __half22float2(*(const __half2*)&hraw.y);
    float4 v;
    v.x = fmaxf(fmaf(f0.x, sc, sh), 0.f);
    v.y = fmaxf(fmaf(f0.y, sc, sh), 0.f);
    v.z = fmaxf(fmaf(f1.x, sc, sh), 0.f);
    v.w = fmaxf(fmaf(f1.y, sc, sh), 0.f);
    ((float4*)out)[f4] = v;
}

// ============================================================
extern "C" void kernel_launch(void* const* d_in, const int* in_sizes, int n_in,
                              void* d_out, int out_size)
{
    (void)in_sizes; (void)n_in; (void)out_size;
    const float* xyz1    = (const float*)d_in[0];
    const float* points1 = (const float*)d_in[1];
    const float* xyz2    = (const float*)d_in[3];
    const float* points2 = (const float*)d_in[4];
    const float* W1      = (const float*)d_in[6];
    const float* b1      = (const float*)d_in[7];
    const float* gamma1  = (const float*)d_in[8];
    const float* beta1   = (const float*)d_in[9];
    const float* W2      = (const float*)d_in[10];
    const float* b2      = (const float*)d_in[11];
    const float* gamma2  = (const float*)d_in[12];
    const float* beta2   = (const float*)d_in[13];
    float* out = (float*)d_out;

    prep_w<<<(C1 * INCH + C2 * C1 + 255) / 256, 256>>>(W1, W2);
    knn_kernel<<<dim3(N1 / 256, BB * GG), 256>>>(xyz1, xyz2);
    y2t_mma<<<dim3(S1 / 128, C1 / 128, BB * GG), 256>>>(points2);
    h1_mma<<<dim3(N1 / 128, C1 / 128, BB * GG), 256>>>(points1, b1);
    bnfinish_kernel<<<dim3(C1, GG), NSLOT>>>(gamma1, beta1, 0);
    gemm2_mma<<<dim3(N1 / 128, C2 / 128, BB * GG), 256>>>(b2);
    bnfinish_kernel<<<dim3(C2, GG), NSLOT>>>(gamma2, beta2, 1);
    bnfinal_kernel<<<(BB * C2 * NTOT) / 4 / 256, 256>>>(out);
}

// round 17
// speedup vs baseline: 1.2681x; 1.0058x over previous
#include <cuda_runtime.h>
#include <cuda_fp16.h>
#include <cstdint>

// Problem constants (fixed by setup_inputs)
#define BB 2
#define GG 16
#define N1 4096
#define S1 1024
#define NTOT 65536   // GG*N1
#define STOT 16384   // GG*S1
#define D1 128
#define D2 256
#define C1 256
#define C2 256
#define INCH 384
#define BN_CNT 8192  // BB*N1 samples per (segment, channel)
#define NSLOT 128    // BN partial slots per (segment, channel)

// -------- device scratch (no allocations allowed) --------
__device__ __half2 g_Y2th[BB * GG][S1][C1 / 2]; // 16.7 MB: (W1b @ p2)^T, fp16
__device__ float4 g_iw0[BB * GG][N1];          // (w0,w1,w2, bits(i0))
__device__ float2 g_iw1[BB * GG][N1];          // (bits(i1), bits(i2))
__device__ __half g_h1h[BB][C1][NTOT];         // 67 MB: layer-1 pre-act, CHANNEL-major
__device__ __half g_h2h[BB][C2][NTOT];         // 67 MB: layer-2 pre-act, channel-major
__device__ __half g_W1h[C1][INCH];             // fp16 weights (pre-converted)
__device__ __half g_W2h[C2][C1];
__device__ float  g_ps[2][GG][C1][NSLOT];      // BN partial sums
__device__ float  g_pq[2][GG][C1][NSLOT];      // BN partial sum-of-squares
__device__ float  g_scale1[GG][C1];
__device__ float  g_shift1[GG][C1];
__device__ float  g_scale2[GG][C2];
__device__ float  g_shift2[GG][C2];

// -------- fp16 helpers --------
__device__ __forceinline__ uint32_t f2h2(float lo, float hi) {
    uint32_t d;
    asm("cvt.rn.f16x2.f32 %0, %1, %2;" : "=r"(d) : "f"(hi), "f"(lo));
    return d;
}

__device__ __forceinline__ void hmma4(float c[4], const uint32_t a[4],
                                      uint32_t b0, uint32_t b1) {
    asm volatile(
        "mma.sync.aligned.m16n8k16.row.col.f32.f16.f16.f32 "
        "{%0,%1,%2,%3},{%4,%5,%6,%7},{%8,%9},{%0,%1,%2,%3};"
        : "+f"(c[0]), "+f"(c[1]), "+f"(c[2]), "+f"(c[3])
        : "r"(a[0]), "r"(a[1]), "r"(a[2]), "r"(a[3]), "r"(b0), "r"(b1));
}

// A-fragment via ldmatrix.x4.trans from As[k][m] (half, pitch 136)
// B-fragment via LDS.32 from Bs[n][k] (half, pitch 24) — conflict-free.
__device__ __forceinline__ void compute_stage(
    const __half (*As)[136], const __half (*Bs)[24],
    float acc[4][4][4], int wm, int wn, int g, int tg, int lane)
{
    const int q  = lane >> 3, r = lane & 7;
    const int mq = (q & 1) * 8;
    const int kq = (q >> 1) * 8;
    uint32_t af[4][4];
    #pragma unroll
    for (int i = 0; i < 4; i++) {
        const int m = wm * 64 + i * 16;
        uint32_t sa = (uint32_t)__cvta_generic_to_shared(&As[kq + r][m + mq]);
        asm volatile(
            "ldmatrix.sync.aligned.m8n8.x4.trans.shared.b16 {%0,%1,%2,%3}, [%4];"
            : "=r"(af[i][0]), "=r"(af[i][1]), "=r"(af[i][2]), "=r"(af[i][3])
            : "r"(sa));
    }
    #pragma unroll
    for (int j = 0; j < 4; j++) {
        const int n = wn * 32 + j * 8 + g;
        const uint32_t b0 = *(const uint32_t*)&Bs[n][2 * tg];
        const uint32_t b1 = *(const uint32_t*)&Bs[n][2 * tg + 8];
        #pragma unroll
        for (int i = 0; i < 4; i++)
            hmma4(acc[i][j], af[i], b0, b1);
    }
}

// Per-thread BN partial reduction (channel-pair layout), for gemm2.
__device__ __forceinline__ void epilogue_stats(
    float ssum[4][2], float sq[4][2], int layer, int gg, int n0,
    int wn, int lane, int slot)
{
    #pragma unroll
    for (int off = 4; off <= 16; off <<= 1) {
        #pragma unroll
        for (int j = 0; j < 4; j++) {
            ssum[j][0] += __shfl_xor_sync(0xffffffffu, ssum[j][0], off);
            ssum[j][1] += __shfl_xor_sync(0xffffffffu, ssum[j][1], off);
            sq[j][0]   += __shfl_xor_sync(0xffffffffu, sq[j][0], off);
            sq[j][1]   += __shfl_xor_sync(0xffffffffu, sq[j][1], off);
        }
    }
    if (lane < 4) {
        #pragma unroll
        for (int j = 0; j < 4; j++) {
            const int c = n0 + wn * 32 + j * 8 + 2 * lane;
            g_ps[layer][gg][c][slot]     = ssum[j][0];
            g_pq[layer][gg][c][slot]     = sq[j][0];
            g_ps[layer][gg][c + 1][slot] = ssum[j][1];
            g_pq[layer][gg][c + 1][slot] = sq[j][1];
        }
    }
}

// ============================================================
// K0: pre-convert weights to fp16 (runs once per launch, ~3 us).
// ============================================================
__global__ __launch_bounds__(256) void prep_w(
    const float* __restrict__ W1, const float* __restrict__ W2)
{
    const int t = blockIdx.x * 256 + threadIdx.x;
    if (t < C1 * INCH) (&g_W1h[0][0])[t] = __float2half(W1[t]);
    const int u = t - C1 * INCH;
    if (u >= 0 && u < C2 * C1) (&g_W2h[0][0])[u] = __float2half(W2[u]);
}

// ============================================================
// K1: 3-NN + inverse-distance weights (dot-product form).
// ============================================================
__global__ __launch_bounds__(256) void knn_kernel(
    const float* __restrict__ xyz1, const float* __restrict__ xyz2)
{
    __shared__ float4 sp[S1];
    const int bg = blockIdx.y;
    const int b = bg >> 4, g = bg & 15;
    const float* x2 = xyz2 + (size_t)b * 3 * STOT + g * S1;
    for (int s = threadIdx.x; s < S1; s += 256) {
        const float x = x2[s], y = x2[STOT + s], z = x2[2 * STOT + s];
        sp[s] = make_float4(x, y, z, 0.5f * fmaf(x, x, fmaf(y, y, z * z)));
    }
    __syncthreads();

    const int n = blockIdx.x * 256 + threadIdx.x;
    const float* x1 = xyz1 + (size_t)b * 3 * NTOT + g * N1 + n;
    const float qx = x1[0], qy = x1[NTOT], qz = x1[2 * NTOT];
    const float qn = fmaf(qx, qx, fmaf(qy, qy, qz * qz));

    float s0 = 3.4e38f, s1 = 3.4e38f, s2 = 3.4e38f;
    int i0 = 0, i1 = 0, i2 = 0;
    #pragma unroll 8
    for (int s = 0; s < S1; s++) {
        const float4 v = sp[s];
        float sc = v.w;
        sc = fmaf(-qx, v.x, sc);
        sc = fmaf(-qy, v.y, sc);
        sc = fmaf(-qz, v.z, sc);
        if (sc < s2) {
            if (sc < s1) {
                if (sc < s0) { s2 = s1; i2 = i1; s1 = s0; i1 = i0; s0 = sc; i0 = s; }
                else         { s2 = s1; i2 = i1; s1 = sc; i1 = s; }
            } else           { s2 = sc; i2 = s; }
        }
    }
    const float d0 = fmaxf(fmaf(2.f, s0, qn), 0.f);
    const float d1 = fmaxf(fmaf(2.f, s1, qn), 0.f);
    const float d2 = fmaxf(fmaf(2.f, s2, qn), 0.f);
    float w0 = 1.0f / (d0 + 1e-8f);
    float w1 = 1.0f / (d1 + 1e-8f);
    float w2 = 1.0f / (d2 + 1e-8f);
    const float inv = 1.0f / (w0 + w1 + w2);
    g_iw0[bg][n] = make_float4(w0 * inv, w1 * inv, w2 * inv, __int_as_float(i0));
    g_iw1[bg][n] = make_float2(__int_as_float(i1), __int_as_float(i2));
}

// A staging (fp32 -> fp16): 256 threads move 16k x 128m per stage.
#define STAGE_STORE_A(Asb, PA)                                          \
    {                                                                   \
        _Pragma("unroll")                                               \
        for (int v = 0; v < 2; v++) {                                   \
            const int kaa = (tid >> 5) + v * 8, maa = (tid & 31) * 4;   \
            uint2 h;                                                    \
            h.x = f2h2(PA[v].x, PA[v].y);                               \
            h.y = f2h2(PA[v].z, PA[v].w);                               \
            *(uint2*)&Asb[kaa][maa] = h;                                \
        }                                                               \
    }

// ============================================================
// K2: Y2t = (W1b @ p2)^T  (fp16 MMA, K=256). grid = (8, 2, 32)
// ============================================================
__global__ __launch_bounds__(256, 2) void y2t_mma(
    const float* __restrict__ p2)
{
    __shared__ __half As[2][16][136];
    __shared__ __half Bs[2][128][24];
    const int m0 = blockIdx.x * 128, n0 = blockIdx.y * 128;
    const int bg = blockIdx.z, b = bg >> 4, gg = bg & 15;
    const int tid = threadIdx.x, lane = tid & 31, wid = tid >> 5;
    const int wm = wid & 1, wn = wid >> 1, g = lane >> 2, tg = lane & 3;

    const float*  Ab = p2 + (size_t)b * D2 * STOT + gg * S1 + m0;
    const __half* Bg = &g_W1h[n0 + (tid >> 1)][128 + (tid & 1) * 8];
    const int nb = tid >> 1, kb = (tid & 1) * 8;

    float acc[4][4][4] = {};
    float4 pa[2][2];
    uint4  pbh[2];
    #pragma unroll
    for (int s = 0; s < 2; s++) {
        #pragma unroll
        for (int v = 0; v < 2; v++)
            pa[s][v] = *(const float4*)(Ab + (size_t)(16 * s + (tid >> 5) + v * 8) * STOT + (tid & 31) * 4);
        pbh[s] = *(const uint4*)(Bg + 16 * s);
    }
    #pragma unroll 2
    for (int s = 0; s < 16; s++) {
        const int set = s & 1;
        STAGE_STORE_A(As[set], pa[set]);
        *(uint4*)&Bs[set][nb][kb] = pbh[set];
        __syncthreads();
        if (s + 2 < 16) {
            const int kt = 16 * (s + 2);
            #pragma unroll
            for (int v = 0; v < 2; v++)
                pa[set][v] = *(const float4*)(Ab + (size_t)(kt + (tid >> 5) + v * 8) * STOT + (tid & 31) * 4);
            pbh[set] = *(const uint4*)(Bg + kt);
        }
        compute_stage(As[set], Bs[set], acc, wm, wn, g, tg, lane);
    }
    #pragma unroll
    for (int i = 0; i < 4; i++) {
        const int s = m0 + wm * 64 + i * 16 + g;
        #pragma unroll
        for (int j = 0; j < 4; j++) {
            const int oh = (n0 + wn * 32 + j * 8) / 2 + tg;
            g_Y2th[bg][s][oh]     = __floats2half2_rn(acc[i][j][0], acc[i][j][1]);
            g_Y2th[bg][s + 8][oh] = __floats2half2_rn(acc[i][j][2], acc[i][j][3]);
        }
    }
}

// ============================================================
// K3: h1_pre = W1a @ p1 + interp(Y2t) + b1 -> CHANNEL-major fp16 store
// + BN1 partials. Doubly-transposed epilogue; float2 acc staging and
// hoisted neighbor metadata. grid = (32, 2, 32)
// ============================================================
__global__ __launch_bounds__(256, 2) void h1_mma(
    const float* __restrict__ p1, const float* __restrict__ b1)
{
    __shared__ __half As[2][16][136];
    __shared__ __half Bs[2][128][24];
    __shared__ float  Tep[8][16][40];   // per-warp transpose tile
    const int m0 = blockIdx.x * 128, n0 = blockIdx.y * 128;
    const int bg = blockIdx.z, b = bg >> 4, gg = bg & 15;
    const int tid = threadIdx.x, lane = tid & 31, wid = tid >> 5;
    const int wm = wid & 1, wn = wid >> 1, g = lane >> 2, tg = lane & 3;

    const float*  Ab = p1 + (size_t)b * D1 * NTOT + gg * N1 + m0;
    const __half* Bg = &g_W1h[n0 + (tid >> 1)][(tid & 1) * 8];
    const int nb = tid >> 1, kb = (tid & 1) * 8;

    float acc[4][4][4] = {};
    float4 pa[2][2];
    uint4  pbh[2];
    #pragma unroll
    for (int s = 0; s < 2; s++) {
        #pragma unroll
        for (int v = 0; v < 2; v++)
            pa[s][v] = *(const float4*)(Ab + (size_t)(16 * s + (tid >> 5) + v * 8) * NTOT + (tid & 31) * 4);
        pbh[s] = *(const uint4*)(Bg + 16 * s);
    }
    #pragma unroll 2
    for (int s = 0; s < 8; s++) {
        const int set = s & 1;
        STAGE_STORE_A(As[set], pa[set]);
        *(uint4*)&Bs[set][nb][kb] = pbh[set];
        __syncthreads();
        if (s + 2 < 8) {
            const int kt = 16 * (s + 2);
            #pragma unroll
            for (int v = 0; v < 2; v++)
                pa[set][v] = *(const float4*)(Ab + (size_t)(kt + (tid >> 5) + v * 8) * NTOT + (tid & 31) * 4);
            pbh[set] = *(const uint4*)(Bg + kt);
        }
        compute_stage(As[set], Bs[set], acc, wm, wn, g, tg, lane);
    }

    // ---- doubly-transposed epilogue ----
    const int chbase = n0 + wn * 32 + tg * 8;     // 8 consecutive channels (gather)
    const float4 bi0 = *(const float4*)(b1 + chbase);
    const float4 bi1 = *(const float4*)(b1 + chbase + 4);
    const float bias8[8] = {bi0.x, bi0.y, bi0.z, bi0.w, bi1.x, bi1.y, bi1.z, bi1.w};
    const int ohb = chbase / 2;
    const int myc = n0 + wn * 32 + lane;          // channel owned for store/stats
    float ssum = 0.f, ssq = 0.f;

    #pragma unroll
    for (int i = 0; i < 4; i++) {
        // hoist neighbor metadata for both rows of this i (overlaps STS below)
        const int rGa = m0 + wm * 64 + i * 16 + g;
        const int rGb = rGa + 8;
        const float4 iwa0 = g_iw0[bg][rGa];
        const float2 iwa1 = g_iw1[bg][rGa];
        const float4 iwb0 = g_iw0[bg][rGb];
        const float2 iwb1 = g_iw1[bg][rGb];
        // (1) acc -> Tep (float2 stores: consecutive channel pairs)
        #pragma unroll
        for (int j = 0; j < 4; j++) {
            *(float2*)&Tep[wid][g][j * 8 + 2 * tg]     = make_float2(acc[i][j][0], acc[i][j][1]);
            *(float2*)&Tep[wid][8 + g][j * 8 + 2 * tg] = make_float2(acc[i][j][2], acc[i][j][3]);
        }
        __syncwarp();
        // (2) gather + interp + bias on (row, 8ch); write fp32 back in place
        #pragma unroll
        for (int h = 0; h < 2; h++) {
            const int lrow = h * 8 + g;
            const int   sidx[3] = {
                h ? __float_as_int(iwb0.w) : __float_as_int(iwa0.w),
                h ? __float_as_int(iwb1.x) : __float_as_int(iwa1.x),
                h ? __float_as_int(iwb1.y) : __float_as_int(iwa1.y)};
            const float wk3[3] = {
                h ? iwb0.x : iwa0.x, h ? iwb0.y : iwa0.y, h ? iwb0.z : iwa0.z};
            const float4 va = *(const float4*)&Tep[wid][lrow][tg * 8];
            const float4 vb = *(const float4*)&Tep[wid][lrow][tg * 8 + 4];
            float v[8] = {va.x, va.y, va.z, va.w, vb.x, vb.y, vb.z, vb.w};
            #pragma unroll
            for (int k = 0; k < 3; k++) {
                const uint4 y  = *(const uint4*)&g_Y2th[bg][sidx[k]][ohb];
                const __half2* yh = (const __half2*)&y;
                const float wk = wk3[k];
                #pragma unroll
                for (int e = 0; e < 4; e++) {
                    const float2 f = __half22float2(yh[e]);
                    v[2 * e]     = fmaf(wk, f.x, v[2 * e]);
                    v[2 * e + 1] = fmaf(wk, f.y, v[2 * e + 1]);
                }
            }
            #pragma unroll
            for (int e = 0; e < 8; e++) v[e] += bias8[e];
            *(float4*)&Tep[wid][lrow][tg * 8]     = make_float4(v[0], v[1], v[2], v[3]);
            *(float4*)&Tep[wid][lrow][tg * 8 + 4] = make_float4(v[4], v[5], v[6], v[7]);
        }
        __syncwarp();
        // (3) column read (my channel x 16 rows) -> 2 STG.128 + stats
        {
            const int rG0 = m0 + wm * 64 + i * 16;
            float vv[16];
            #pragma unroll
            for (int r = 0; r < 16; r++) vv[r] = Tep[wid][r][lane];
            uint4 st0, st1;
            uint32_t* s0 = (uint32_t*)&st0;
            uint32_t* s1 = (uint32_t*)&st1;
            #pragma unroll
            for (int e = 0; e < 4; e++) {
                s0[e] = f2h2(vv[2 * e], vv[2 * e + 1]);
                s1[e] = f2h2(vv[8 + 2 * e], vv[9 + 2 * e]);
            }
            *(uint4*)&g_h1h[b][myc][gg * N1 + rG0]     = st0;
            *(uint4*)&g_h1h[b][myc][gg * N1 + rG0 + 8] = st1;
            #pragma unroll
            for (int r = 0; r < 16; r++) {
                ssum += vv[r];
                ssq = fmaf(vv[r], vv[r], ssq);
            }
        }
        __syncwarp();
    }
    const int slot = b * 64 + blockIdx.x * 2 + wm;
    g_ps[0][gg][myc][slot] = ssum;
    g_pq[0][gg][myc][slot] = ssq;
}

// ============================================================
// K4/K6: finish BN stats (deterministic tree over NSLOT partials).
// ============================================================
__global__ __launch_bounds__(NSLOT) void bnfinish_kernel(
    const float* __restrict__ gamma, const float* __restrict__ beta, int layer)
{
    const int c = blockIdx.x, gg = blockIdx.y, tid = threadIdx.x;
    __shared__ float rs[NSLOT], rq[NSLOT];
    rs[tid] = g_ps[layer][gg][c][tid];
    rq[tid] = g_pq[layer][gg][c][tid];
    __syncthreads();
    for (int off = NSLOT / 2; off; off >>= 1) {
        if (tid < off) { rs[tid] += rs[tid + off]; rq[tid] += rq[tid + off]; }
        __syncthreads();
    }
    if (tid == 0) {
        const float inv = 1.0f / (float)BN_CNT;
        const float mean = rs[0] * inv;
        const float var = rq[0] * inv - mean * mean;
        const float sc = gamma[c] * rsqrtf(var + 1e-5f);
        const float sh = beta[c] - mean * sc;
        if (layer == 0) { g_scale1[gg][c] = sc; g_shift1[gg][c] = sh; }
        else            { g_scale2[gg][c] = sc; g_shift2[gg][c] = sh; }
    }
}

// ============================================================
// K5: h2_pre = W2 @ relu(bn1(h1)) + b2 -> fp16 store + BN2 partials.
// BN1 scale/shift cached in smem as half (loaded once); channel-major A,
// k-major smem, trans ldmatrix. grid = (32, 2, 32)
// ============================================================
__global__ __launch_bounds__(256, 2) void gemm2_mma(
    const float* __restrict__ b2)
{
    __shared__ __half As[2][16][136];
    __shared__ __half Bs[2][128][24];
    __shared__ __half sS[C1], sH[C1];
    const int m0 = blockIdx.x * 128, n0 = blockIdx.y * 128;
    const int bg = blockIdx.z, b = bg >> 4, gg = bg & 15;
    const int tid = threadIdx.x, lane = tid & 31, wid = tid >> 5;
    const int wm = wid & 1, wn = wid >> 1, g = lane >> 2, tg = lane & 3;

    // one-time BN param cache (fp32 -> fp16)
    sS[tid] = __float2half(g_scale1[gg][tid]);
    sH[tid] = __float2half(g_shift1[gg][tid]);

    const __half* Abh = &g_h1h[b][0][gg * N1 + m0];
    const __half* Bg  = &g_W2h[n0 + (tid >> 1)][(tid & 1) * 8];
    const int nb = tid >> 1, kb = (tid & 1) * 8;

    float acc[4][4][4] = {};
    const int ka = tid >> 4, ma = (tid & 15) * 8;
    uint4 pha[2], pbh[2];
    #pragma unroll
    for (int s = 0; s < 2; s++) {
        pha[s] = *(const uint4*)(Abh + (size_t)(16 * s + ka) * NTOT + ma);
        pbh[s] = *(const uint4*)(Bg + 16 * s);
    }
    __syncthreads();   // sS/sH visible

    const __half2 hz = __float2half2_rn(0.f);
    #pragma unroll 2
    for (int s = 0; s < 16; s++) {
        const int set = s & 1;
        // A: BN1 + ReLU in half2 (params from smem), store to As[k][m]
        {
            const int c = 16 * s + ka;
            const __half2 psc = __half2half2(sS[c]);
            const __half2 psh = __half2half2(sH[c]);
            const __half2* hp = (const __half2*)&pha[set];
            uint4 st;
            __half2* sp = (__half2*)&st;
            #pragma unroll
            for (int u = 0; u < 4; u++)
                sp[u] = __hmax2(__hfma2(hp[u], psc, psh), hz);
            *(uint4*)&As[set][ka][ma] = st;
        }
        *(uint4*)&Bs[set][nb][kb] = pbh[set];
        __syncthreads();
        if (s + 2 < 16) {
            pha[set] = *(const uint4*)(Abh + (size_t)(16 * (s + 2) + ka) * NTOT + ma);
            pbh[set] = *(const uint4*)(Bg + 16 * (s + 2));
        }
        compute_stage(As[set], Bs[set], acc, wm, wn, g, tg, lane);
    }

    // Epilogue: +bias, fp16 store to g_h2h (channel-major), BN2 partials.
    float ssum[4][2] = {}, sq[4][2] = {};
    #pragma unroll
    for (int i = 0; i < 4; i++) {
        const int rA = m0 + wm * 64 + i * 16 + g;
        const int rB = rA + 8;
        #pragma unroll
        for (int j = 0; j < 4; j++) {
            const int o = n0 + wn * 32 + j * 8 + 2 * tg;
            const float2 bo = *(const float2*)(b2 + o);
            const float c0 = acc[i][j][0] + bo.x;
            const float c1 = acc[i][j][1] + bo.y;
            const float c2 = acc[i][j][2] + bo.x;
            const float c3 = acc[i][j][3] + bo.y;
            g_h2h[b][o][gg * N1 + rA]     = __float2half(c0);
            g_h2h[b][o + 1][gg * N1 + rA] = __float2half(c1);
            g_h2h[b][o][gg * N1 + rB]     = __float2half(c2);
            g_h2h[b][o + 1][gg * N1 + rB] = __float2half(c3);
            ssum[j][0] += c0 + c2; sq[j][0] += c0 * c0 + c2 * c2;
            ssum[j][1] += c1 + c3; sq[j][1] += c1 * c1 + c3 * c3;
        }
    }
    epilogue_stats(ssum, sq, 1, gg, n0, wn, lane, b * 64 + blockIdx.x * 2 + wm);
}

// ============================================================
// K7: BN2 + ReLU: fp16 g_h2h -> fp32 d_out.
// ============================================================
__global__ __launch_bounds__(256) void bnfinal_kernel(float* __restrict__ out)
{
    const size_t f4 = (size_t)blockIdx.x * 256 + threadIdx.x;
    const size_t f = f4 * 4;
    const int o = (int)((f >> 16) & 255);
    const int g = (int)((f >> 12) & 15);
    const float sc = g_scale2[g][o];
    const float sh = g_shift2[g][o];
    const uint2 hraw = ((const uint2*)&g_h2h[0][0][0])[f4];
    const float2 f0 = __half22float2(*(const __half2*)&hraw.x);
    const float2 f1 = __half22float2(*(const __half2*)&hraw.y);
    float4 v;
    v.x = fmaxf(fmaf(f0.x, sc, sh), 0.f);
    v.y = fmaxf(fmaf(f0.y, sc, sh), 0.f);
    v.z = fmaxf(fmaf(f1.x, sc, sh), 0.f);
    v.w = fmaxf(fmaf(f1.y, sc, sh), 0.f);
    ((float4*)out)[f4] = v;
}

// ============================================================
extern "C" void kernel_launch(void* const* d_in, const int* in_sizes, int n_in,
                              void* d_out, int out_size)
{
    (void)in_sizes; (void)n_in; (void)out_size;
    const float* xyz1    = (const float*)d_in[0];
    const float* points1 = (const float*)d_in[1];
    const float* xyz2    = (const float*)d_in[3];
    const float* points2 = (const float*)d_in[4];
    const float* W1      = (const float*)d_in[6];
    const float* b1      = (const float*)d_in[7];
    const float* gamma1  = (const float*)d_in[8];
    const float* beta1   = (const float*)d_in[9];
    const float* W2      = (const float*)d_in[10];
    const float* b2      = (const float*)d_in[11];
    const float* gamma2  = (const float*)d_in[12];
    const float* beta2   = (const float*)d_in[13];
    float* out = (float*)d_out;

    prep_w<<<(C1 * INCH + C2 * C1 + 255) / 256, 256>>>(W1, W2);
    knn_kernel<<<dim3(N1 / 256, BB * GG), 256>>>(xyz1, xyz2);
    y2t_mma<<<dim3(S1 / 128, C1 / 128, BB * GG), 256>>>(points2);
    h1_mma<<<dim3(N1 / 128, C1 / 128, BB * GG), 256>>>(points1, b1);
    bnfinish_kernel<<<dim3(C1, GG), NSLOT>>>(gamma1, beta1, 0);
    gemm2_mma<<<dim3(N1 / 128, C2 / 128, BB * GG), 256>>>(b2);
    bnfinish_kernel<<<dim3(C2, GG), NSLOT>>>(gamma2, beta2, 1);
    bnfinal_kernel<<<(BB * C2 * NTOT) / 4 / 256, 256>>>(out);
}